// round 1
// baseline (speedup 1.0000x reference)
#include <cuda_runtime.h>
#include <cuda_bf16.h>
#include <cstdint>
#include <cstddef>

// Problem constants
#define BATCH   8
#define HH      56
#define WW      56
#define CCH     384
#define HEADS   6
#define DH      64
#define PQ      784        // 28*28 tokens after stride-2 / pool
#define SS      196        // 14*14 residual source grid
#define TT      784        // key/residual-channel count

// ---------------- scratch (device globals; no runtime allocation) -------------
__device__ float g_Qln[BATCH * PQ * CCH];
__device__ float g_KV [BATCH * PQ * CCH];
__device__ float g_Qh [BATCH * PQ * CCH];
__device__ float g_Kh [BATCH * PQ * CCH];
__device__ float g_Vh [BATCH * PQ * CCH];
__device__ float g_Rm [BATCH * HEADS * SS * TT];      // pre-mixed residual (29.5 MB)
__device__ float g_P  [(size_t)BATCH * HEADS * PQ * TT]; // scores -> softmaxed in place (118 MB)
__device__ float g_AV [BATCH * PQ * CCH];

// ---------------- kernel 1: depthwise conv (stride2,pad1) + LN, and 2x2 avgpool
__global__ void prep_k(const float* __restrict__ x, const float* __restrict__ cw,
                       const float* __restrict__ lng, const float* __restrict__ lnb,
                       float* __restrict__ Qln, float* __restrict__ KV)
{
    int p = blockIdx.x;          // 0..783
    int b = blockIdx.y;          // 0..7
    int c = threadIdx.x;         // 0..383
    int oy = p / 28, ox = p % 28;
    const float* xb = x + (size_t)b * (HH * WW) * CCH;

    // depthwise conv
    float acc = 0.f;
    #pragma unroll
    for (int dy = 0; dy < 3; dy++) {
        int y = 2 * oy + dy - 1;
        if ((unsigned)y < (unsigned)HH) {
            #pragma unroll
            for (int dx = 0; dx < 3; dx++) {
                int xx = 2 * ox + dx - 1;
                if ((unsigned)xx < (unsigned)WW)
                    acc += xb[(size_t)(y * WW + xx) * CCH + c] * cw[c * 9 + dy * 3 + dx];
            }
        }
    }

    // 2x2 avg pool
    int py = 2 * oy, px = 2 * ox;
    float pv = 0.25f * (xb[(size_t)(py * WW + px) * CCH + c] +
                        xb[(size_t)(py * WW + px + 1) * CCH + c] +
                        xb[(size_t)((py + 1) * WW + px) * CCH + c] +
                        xb[(size_t)((py + 1) * WW + px + 1) * CCH + c]);
    KV[((size_t)b * PQ + p) * CCH + c] = pv;

    // LayerNorm over channels
    __shared__ float ssum[CCH];
    __shared__ float ssq [CCH];
    ssum[c] = acc; ssq[c] = acc * acc;
    __syncthreads();
    if (c < 128) { ssum[c] += ssum[c + 128] + ssum[c + 256];
                   ssq [c] += ssq [c + 128] + ssq [c + 256]; }
    __syncthreads();
    for (int s = 64; s > 0; s >>= 1) {
        if (c < s) { ssum[c] += ssum[c + s]; ssq[c] += ssq[c + s]; }
        __syncthreads();
    }
    float mu  = ssum[0] * (1.f / CCH);
    float var = ssq[0] * (1.f / CCH) - mu * mu;
    float inv = rsqrtf(var + 1e-5f);
    Qln[((size_t)b * PQ + p) * CCH + c] = (acc - mu) * inv * lng[c] + lnb[c];
}

// ---------------- kernel 2: generic tiled GEMM -------------------------------
// MODE 0: C[m,n] = sum_k A[m,k] * W[n,k] (+bias), single batch
// MODE 1: AV mode: z -> (b,o);  C[l,d] = sum_t P[bo,l,t] * Vh[b,t,o*64+d]
template <int MODE>
__global__ void gemm_k(const float* __restrict__ Ag, const float* __restrict__ Bg,
                       const float* __restrict__ bias, float* __restrict__ Cg,
                       int M, int N, int K, int lda, int ldb, int ldc)
{
    __shared__ float As[16][132];   // [k][m], padded
    __shared__ float Bs[16][64];    // [k][n]

    const float* A; const float* Bm; float* C;
    if (MODE == 0) { A = Ag; Bm = Bg; C = Cg; }
    else {
        int z = blockIdx.z; int bb = z / HEADS, o = z % HEADS;
        A  = Ag + (size_t)z * PQ * TT;
        Bm = Bg + (size_t)bb * PQ * CCH + o * DH;
        C  = Cg + (size_t)bb * PQ * CCH + o * DH;
    }
    int m0 = blockIdx.y * 128, n0 = blockIdx.x * 64;
    int tid = threadIdx.x;
    int ty = tid >> 4, tx = tid & 15;
    float acc[8][4];
    #pragma unroll
    for (int i = 0; i < 8; i++)
        #pragma unroll
        for (int j = 0; j < 4; j++) acc[i][j] = 0.f;

    for (int k0 = 0; k0 < K; k0 += 16) {
        #pragma unroll
        for (int i = 0; i < 8; i++) {
            int idx = tid + i * 256; int kk = idx & 15; int m = idx >> 4;
            int gm = m0 + m;
            As[kk][m] = (gm < M) ? A[(size_t)gm * lda + k0 + kk] : 0.f;
        }
        #pragma unroll
        for (int i = 0; i < 4; i++) {
            int idx = tid + i * 256;
            if (MODE == 0) {
                int kk = idx & 15; int n = idx >> 4;
                Bs[kk][n] = Bm[(size_t)(n0 + n) * ldb + k0 + kk];
            } else {
                int n = idx & 63; int kk = idx >> 6;
                Bs[kk][n] = Bm[(size_t)(k0 + kk) * ldb + n0 + n];
            }
        }
        __syncthreads();
        #pragma unroll
        for (int kk = 0; kk < 16; kk++) {
            float4 a0 = *(const float4*)&As[kk][ty * 8];
            float4 a1 = *(const float4*)&As[kk][ty * 8 + 4];
            float4 b0 = *(const float4*)&Bs[kk][tx * 4];
            float av[8] = {a0.x, a0.y, a0.z, a0.w, a1.x, a1.y, a1.z, a1.w};
            float bv[4] = {b0.x, b0.y, b0.z, b0.w};
            #pragma unroll
            for (int i = 0; i < 8; i++)
                #pragma unroll
                for (int j = 0; j < 4; j++)
                    acc[i][j] += av[i] * bv[j];
        }
        __syncthreads();
    }
    #pragma unroll
    for (int i = 0; i < 8; i++) {
        int gm = m0 + ty * 8 + i;
        if (gm < M) {
            #pragma unroll
            for (int j = 0; j < 4; j++) {
                int gn = n0 + tx * 4 + j;
                float v = acc[i][j];
                if (MODE == 0 && bias != nullptr) v += bias[gn];
                C[(size_t)gm * ldc + gn] = v;
            }
        }
    }
}

// ---------------- kernel 3: pre-mix residual over source heads ----------------
// Rm[b,o,s,t] = sum_h wf[o, 6+h] * res_attn[b,h,s,t]
__global__ void rmix_k(const float* __restrict__ ra, const float* __restrict__ wf,
                       float* __restrict__ Rm)
{
    int s = blockIdx.x;   // 0..195
    int b = blockIdx.y;   // 0..7
    __shared__ float w[HEADS][HEADS];
    if (threadIdx.x < 36)
        w[threadIdx.x / 6][threadIdx.x % 6] = wf[(threadIdx.x / 6) * 12 + 6 + (threadIdx.x % 6)];
    __syncthreads();
    for (int t = threadIdx.x; t < TT; t += blockDim.x) {
        float r[HEADS];
        #pragma unroll
        for (int h = 0; h < HEADS; h++)
            r[h] = ra[(((size_t)b * HEADS + h) * SS + s) * TT + t];
        #pragma unroll
        for (int o = 0; o < HEADS; o++) {
            float v = 0.f;
            #pragma unroll
            for (int h = 0; h < HEADS; h++) v += w[o][h] * r[h];
            Rm[(((size_t)b * HEADS + o) * SS + s) * TT + t] = v;
        }
    }
}

// ---------------- kernel 4: fused score (QK^T per head + head mix + bilinear) -
// grid (25,25,8), 256 thr, dynamic smem: Qs[384][36] Ks[384][36] Dsm[6][32][32]
__global__ void score_k(const float* __restrict__ Qh, const float* __restrict__ Kh,
                        const float* __restrict__ Rm, const float* __restrict__ wf,
                        const float* __restrict__ bf, float* __restrict__ P)
{
    extern __shared__ float sm[];
    float* Qs  = sm;                 // [c][l], stride 36
    float* Ks  = sm + 384 * 36;     // [c][t], stride 36
    float* Dsm = Ks + 384 * 36;     // [6][32][32]
    __shared__ int   bly0[32], bly1[32], blx0[32], blx1[32];
    __shared__ float blwy[32], blwx[32];
    __shared__ float wfs[HEADS][HEADS], bfs[HEADS];

    int b  = blockIdx.z;
    int l0 = blockIdx.y * 32;
    int t0 = blockIdx.x * 32;
    int tid = threadIdx.x;

    if (tid < 36) wfs[tid / 6][tid % 6] = wf[(tid / 6) * 12 + (tid % 6)];
    if (tid < 6)  bfs[tid] = bf[tid];
    if (tid < 32) {
        int gl = min(l0 + tid, PQ - 1);
        int y = gl / 28, xx = gl % 28;
        float cy = fminf(fmaxf((y + 0.5f) * 0.5f - 0.5f, 0.f), 13.f);
        int iy0 = (int)floorf(cy); float wy = cy - (float)iy0; int iy1 = min(iy0 + 1, 13);
        float cx = fminf(fmaxf((xx + 0.5f) * 0.5f - 0.5f, 0.f), 13.f);
        int ix0 = (int)floorf(cx); float wx = cx - (float)ix0; int ix1 = min(ix0 + 1, 13);
        bly0[tid] = iy0; bly1[tid] = iy1; blwy[tid] = wy;
        blx0[tid] = ix0; blx1[tid] = ix1; blwx[tid] = wx;
    }

    const float* Qb = Qh + (size_t)b * PQ * CCH;
    const float* Kb = Kh + (size_t)b * PQ * CCH;
    for (int idx = tid; idx < 32 * CCH; idx += 256) {
        int l = idx / CCH, c = idx % CCH;
        int gl = l0 + l, gt = t0 + l;
        Qs[c * 36 + l] = (gl < PQ) ? Qb[(size_t)gl * CCH + c] : 0.f;
        Ks[c * 36 + l] = (gt < PQ) ? Kb[(size_t)gt * CCH + c] : 0.f;
    }
    __syncthreads();

    // Phase D: per-head raw dot products, 96 threads, 8x8 micro-tiles
    if (tid < 96) {
        int h = tid / 16, sub = tid % 16;
        int lt = (sub >> 2) * 8, tt2 = (sub & 3) * 8;
        float acc[8][8];
        #pragma unroll
        for (int i = 0; i < 8; i++)
            #pragma unroll
            for (int j = 0; j < 8; j++) acc[i][j] = 0.f;
        const float* q = Qs + h * DH * 36 + lt;
        const float* k = Ks + h * DH * 36 + tt2;
        #pragma unroll 4
        for (int c = 0; c < DH; c++) {
            float4 qa = *(const float4*)(q + c * 36);
            float4 qb2 = *(const float4*)(q + c * 36 + 4);
            float4 ka = *(const float4*)(k + c * 36);
            float4 kb2 = *(const float4*)(k + c * 36 + 4);
            float qv[8] = {qa.x, qa.y, qa.z, qa.w, qb2.x, qb2.y, qb2.z, qb2.w};
            float kv[8] = {ka.x, ka.y, ka.z, ka.w, kb2.x, kb2.y, kb2.z, kb2.w};
            #pragma unroll
            for (int i = 0; i < 8; i++)
                #pragma unroll
                for (int j = 0; j < 8; j++)
                    acc[i][j] += qv[i] * kv[j];
        }
        #pragma unroll
        for (int i = 0; i < 8; i++)
            #pragma unroll
            for (int j = 0; j < 8; j++)
                Dsm[h * 1024 + (lt + i) * 32 + (tt2 + j)] = acc[i][j];
    }
    __syncthreads();

    // Phase mix: P[o,l,t] = bias + sum_h wf*scale*D + bilinear(Rmix)
    const float scale = rsqrtf((float)CCH);
    float* Pb = P + (size_t)b * HEADS * PQ * TT;
    const float* Rb = Rm + (size_t)b * HEADS * SS * TT;
    for (int idx = tid; idx < HEADS * 1024; idx += 256) {
        int o = idx >> 10; int r = idx & 1023;
        int l = r >> 5, t = r & 31;
        int gl = l0 + l, gt = t0 + t;
        if (gl < PQ && gt < TT) {
            float pval = bfs[o];
            #pragma unroll
            for (int h = 0; h < HEADS; h++)
                pval += wfs[o][h] * scale * Dsm[h * 1024 + r];
            const float* R = Rb + (size_t)o * SS * TT + gt;
            int y0 = bly0[l], y1 = bly1[l], x0 = blx0[l], x1 = blx1[l];
            float wy = blwy[l], wx = blwx[l];
            float v00 = R[(size_t)(y0 * 14 + x0) * TT];
            float v01 = R[(size_t)(y0 * 14 + x1) * TT];
            float v10 = R[(size_t)(y1 * 14 + x0) * TT];
            float v11 = R[(size_t)(y1 * 14 + x1) * TT];
            float r0 = v00 + (v01 - v00) * wx;
            float r1 = v10 + (v11 - v10) * wx;
            pval += r0 + (r1 - r0) * wy;
            Pb[((size_t)o * PQ + gl) * TT + gt] = pval;
        }
    }
}

// ---------------- kernel 5: row softmax over t=784 ----------------------------
__global__ void softmax_k(float* __restrict__ P)
{
    size_t row = blockIdx.x;
    float* p = P + row * TT;
    __shared__ float red[256];
    int tid = threadIdx.x;

    float m = -1e30f;
    for (int t = tid; t < TT; t += 256) m = fmaxf(m, p[t]);
    red[tid] = m; __syncthreads();
    for (int s = 128; s > 0; s >>= 1) {
        if (tid < s) red[tid] = fmaxf(red[tid], red[tid + s]);
        __syncthreads();
    }
    m = red[0];
    __syncthreads();

    float sum = 0.f;
    for (int t = tid; t < TT; t += 256) {
        float e = __expf(p[t] - m);
        p[t] = e; sum += e;
    }
    red[tid] = sum; __syncthreads();
    for (int s = 128; s > 0; s >>= 1) {
        if (tid < s) red[tid] += red[tid + s];
        __syncthreads();
    }
    float inv = 1.f / red[0];
    for (int t = tid; t < TT; t += 256) p[t] *= inv;
}

// ---------------- launcher ----------------------------------------------------
extern "C" void kernel_launch(void* const* d_in, const int* in_sizes, int n_in,
                              void* d_out, int out_size)
{
    const float* x   = (const float*)d_in[0];
    const float* ra  = (const float*)d_in[1];
    const float* cw  = (const float*)d_in[2];
    const float* lng = (const float*)d_in[3];
    const float* lnb = (const float*)d_in[4];
    const float* wq  = (const float*)d_in[5];
    const float* wk  = (const float*)d_in[6];
    const float* wv  = (const float*)d_in[7];
    const float* wp  = (const float*)d_in[8];
    const float* bp  = (const float*)d_in[9];
    const float* wf  = (const float*)d_in[10];
    const float* bf  = (const float*)d_in[11];
    float* out = (float*)d_out;

    float *Qln, *KV, *Qh, *Kh, *Vh, *Rm, *P, *AV;
    cudaGetSymbolAddress((void**)&Qln, g_Qln);
    cudaGetSymbolAddress((void**)&KV,  g_KV);
    cudaGetSymbolAddress((void**)&Qh,  g_Qh);
    cudaGetSymbolAddress((void**)&Kh,  g_Kh);
    cudaGetSymbolAddress((void**)&Vh,  g_Vh);
    cudaGetSymbolAddress((void**)&Rm,  g_Rm);
    cudaGetSymbolAddress((void**)&P,   g_P);
    cudaGetSymbolAddress((void**)&AV,  g_AV);

    // 1. conv+LN and pool
    prep_k<<<dim3(PQ, BATCH), CCH>>>(x, cw, lng, lnb, Qln, KV);

    // 2. Q/K/V projections (M=6272, N=384, K=384)
    const int M = BATCH * PQ;
    gemm_k<0><<<dim3(6, 49, 1), 256>>>(Qln, wq, nullptr, Qh, M, CCH, CCH, CCH, CCH, CCH);
    gemm_k<0><<<dim3(6, 49, 1), 256>>>(KV,  wk, nullptr, Kh, M, CCH, CCH, CCH, CCH, CCH);
    gemm_k<0><<<dim3(6, 49, 1), 256>>>(KV,  wv, nullptr, Vh, M, CCH, CCH, CCH, CCH, CCH);

    // 3. residual pre-mix
    rmix_k<<<dim3(SS, BATCH), 256>>>(ra, wf, Rm);

    // 4. fused scores
    int smem = (384 * 36 * 2 + HEADS * 1024) * (int)sizeof(float); // 135168
    cudaFuncSetAttribute(score_k, cudaFuncAttributeMaxDynamicSharedMemorySize, smem);
    score_k<<<dim3(25, 25, BATCH), 256, smem>>>(Qh, Kh, Rm, wf, bf, P);

    // 5. softmax (one block per row)
    softmax_k<<<BATCH * HEADS * PQ, 256>>>(P);

    // 6. attn @ V  (batched: 48 x [784x64x784])
    gemm_k<1><<<dim3(1, 7, BATCH * HEADS), 256>>>(P, Vh, nullptr, AV, PQ, DH, TT, TT, CCH, CCH);

    // 7. output projection + bias -> d_out
    gemm_k<0><<<dim3(6, 49, 1), 256>>>(AV, wp, bp, out, M, CCH, CCH, CCH, CCH, CCH);
}

// round 2
// speedup vs baseline: 1.2256x; 1.2256x over previous
#include <cuda_runtime.h>
#include <cuda_bf16.h>
#include <cstdint>
#include <cstddef>

// Problem constants
#define BATCH   8
#define HH      56
#define WW      56
#define CCH     384
#define HEADS   6
#define DH      64
#define PQ      784        // 28*28 tokens after stride-2 / pool
#define SS      196        // 14*14 residual source grid
#define TT      784        // key count

// ---------------- scratch (device globals; no runtime allocation) -------------
__device__ float g_Qln[BATCH * PQ * CCH];
__device__ float g_KV [BATCH * PQ * CCH];
__device__ float g_Qh [BATCH * PQ * CCH];
__device__ float g_Kh [BATCH * PQ * CCH];
__device__ float g_Vh [BATCH * PQ * CCH];
__device__ float g_Rm [BATCH * HEADS * SS * TT];   // pre-mixed residual (29.5 MB)
__device__ float g_AV [BATCH * PQ * CCH];

// ---------------- kernel 1: depthwise conv (stride2,pad1) + LN, and 2x2 avgpool
__global__ void prep_k(const float* __restrict__ x, const float* __restrict__ cw,
                       const float* __restrict__ lng, const float* __restrict__ lnb,
                       float* __restrict__ Qln, float* __restrict__ KV)
{
    int p = blockIdx.x;          // 0..783
    int b = blockIdx.y;          // 0..7
    int c = threadIdx.x;         // 0..383
    int oy = p / 28, ox = p % 28;
    const float* xb = x + (size_t)b * (HH * WW) * CCH;

    float acc = 0.f;
    #pragma unroll
    for (int dy = 0; dy < 3; dy++) {
        int y = 2 * oy + dy - 1;
        if ((unsigned)y < (unsigned)HH) {
            #pragma unroll
            for (int dx = 0; dx < 3; dx++) {
                int xx = 2 * ox + dx - 1;
                if ((unsigned)xx < (unsigned)WW)
                    acc += xb[(size_t)(y * WW + xx) * CCH + c] * cw[c * 9 + dy * 3 + dx];
            }
        }
    }

    int py = 2 * oy, px = 2 * ox;
    float pv = 0.25f * (xb[(size_t)(py * WW + px) * CCH + c] +
                        xb[(size_t)(py * WW + px + 1) * CCH + c] +
                        xb[(size_t)((py + 1) * WW + px) * CCH + c] +
                        xb[(size_t)((py + 1) * WW + px + 1) * CCH + c]);
    KV[((size_t)b * PQ + p) * CCH + c] = pv;

    __shared__ float ssum[CCH];
    __shared__ float ssq [CCH];
    ssum[c] = acc; ssq[c] = acc * acc;
    __syncthreads();
    if (c < 128) { ssum[c] += ssum[c + 128] + ssum[c + 256];
                   ssq [c] += ssq [c + 128] + ssq [c + 256]; }
    __syncthreads();
    for (int s = 64; s > 0; s >>= 1) {
        if (c < s) { ssum[c] += ssum[c + s]; ssq[c] += ssq[c + s]; }
        __syncthreads();
    }
    float mu  = ssum[0] * (1.f / CCH);
    float var = ssq[0] * (1.f / CCH) - mu * mu;
    float inv = rsqrtf(var + 1e-5f);
    Qln[((size_t)b * PQ + p) * CCH + c] = (acc - mu) * inv * lng[c] + lnb[c];
}

// ---------------- kernel 2: 128x128-tile GEMM, C = A * W^T (+bias) -----------
// A[M][384] row-major, W[N][384] row-major. M multiple of 128, N multiple of 128.
__global__ void __launch_bounds__(256) gemm2_k(const float* __restrict__ A,
                                               const float* __restrict__ W,
                                               const float* __restrict__ bias,
                                               float* __restrict__ C, int M, int N)
{
    __shared__ float As[8][132];
    __shared__ float Bs[8][132];
    int m0 = blockIdx.y * 128, n0 = blockIdx.x * 128;
    int tid = threadIdx.x;
    int ty = tid >> 4, tx = tid & 15;
    int lr = tid >> 1, lk = (tid & 1) * 4;

    float accr[8][8];
    #pragma unroll
    for (int i = 0; i < 8; i++)
        #pragma unroll
        for (int j = 0; j < 8; j++) accr[i][j] = 0.f;

    for (int k0 = 0; k0 < CCH; k0 += 8) {
        float4 av = *(const float4*)&A[(size_t)(m0 + lr) * CCH + k0 + lk];
        float4 bv = *(const float4*)&W[(size_t)(n0 + lr) * CCH + k0 + lk];
        __syncthreads();
        As[lk + 0][lr] = av.x; As[lk + 1][lr] = av.y;
        As[lk + 2][lr] = av.z; As[lk + 3][lr] = av.w;
        Bs[lk + 0][lr] = bv.x; Bs[lk + 1][lr] = bv.y;
        Bs[lk + 2][lr] = bv.z; Bs[lk + 3][lr] = bv.w;
        __syncthreads();
        #pragma unroll
        for (int kk = 0; kk < 8; kk++) {
            float4 a0 = *(const float4*)&As[kk][ty * 8];
            float4 a1 = *(const float4*)&As[kk][ty * 8 + 4];
            float4 b0 = *(const float4*)&Bs[kk][tx * 8];
            float4 b1 = *(const float4*)&Bs[kk][tx * 8 + 4];
            float avv[8] = {a0.x, a0.y, a0.z, a0.w, a1.x, a1.y, a1.z, a1.w};
            float bvv[8] = {b0.x, b0.y, b0.z, b0.w, b1.x, b1.y, b1.z, b1.w};
            #pragma unroll
            for (int i = 0; i < 8; i++)
                #pragma unroll
                for (int j = 0; j < 8; j++)
                    accr[i][j] += avv[i] * bvv[j];
        }
    }
    #pragma unroll
    for (int i = 0; i < 8; i++) {
        int gm = m0 + ty * 8 + i;
        #pragma unroll
        for (int j = 0; j < 8; j++) {
            int gn = n0 + tx * 8 + j;
            float v = accr[i][j];
            if (bias != nullptr) v += bias[gn];
            C[(size_t)gm * N + gn] = v;
        }
    }
}

// ---------------- kernel 3: pre-mix residual over source heads ----------------
__global__ void rmix_k(const float* __restrict__ ra, const float* __restrict__ wf,
                       float* __restrict__ Rm)
{
    int s = blockIdx.x;   // 0..195
    int b = blockIdx.y;   // 0..7
    __shared__ float w[HEADS][HEADS];
    if (threadIdx.x < 36)
        w[threadIdx.x / 6][threadIdx.x % 6] = wf[(threadIdx.x / 6) * 12 + 6 + (threadIdx.x % 6)];
    __syncthreads();
    for (int t = threadIdx.x; t < TT; t += blockDim.x) {
        float r[HEADS];
        #pragma unroll
        for (int h = 0; h < HEADS; h++)
            r[h] = ra[(((size_t)b * HEADS + h) * SS + s) * TT + t];
        #pragma unroll
        for (int o = 0; o < HEADS; o++) {
            float v = 0.f;
            #pragma unroll
            for (int h = 0; h < HEADS; h++) v += w[o][h] * r[h];
            Rm[(((size_t)b * HEADS + o) * SS + s) * TT + t] = v;
        }
    }
}

// ---------------- kernel 4: fused flash attention -----------------------------
// One block per (b, 32-query tile). Streams 32-key K/V tiles.
// Per tile: D[h,l,t] (per-head dots) -> head-mix + bias + bilinear residual ->
// online softmax -> AV accumulation. Eliminates the P tensor entirely.
__global__ void __launch_bounds__(256) flash_k(
    const float* __restrict__ Qh, const float* __restrict__ Kh,
    const float* __restrict__ Vh, const float* __restrict__ Rm,
    const float* __restrict__ wf, const float* __restrict__ bf,
    float* __restrict__ AVo)
{
    extern __shared__ float sm[];
    float* Qs = sm;                         // [384][36]  (c-major, padded)
    float* Ks = Qs + 384 * 36;              // [384][36]
    float* Vs = Ks + 384 * 36;              // [32][384]  (t-major)
    float* Ps = Vs + 32 * 384;              // [6][32][33]
    __shared__ float wfs[HEADS][HEADS], bfs[HEADS];
    __shared__ int   by0[32], by1[32], bx0[32], bx1[32];
    __shared__ float bwy[32], bwx[32];

    int b  = blockIdx.y;
    int l0 = blockIdx.x * 32;
    int tid = threadIdx.x;
    const float scale = rsqrtf((float)CCH);

    if (tid < 36) wfs[tid / 6][tid % 6] = wf[(tid / 6) * 12 + (tid % 6)] * scale;
    if (tid < 6)  bfs[tid] = bf[tid];
    if (tid < 32) {
        int gl = min(l0 + tid, PQ - 1);
        int y = gl / 28, xx = gl % 28;
        float cy = fminf(fmaxf((y + 0.5f) * 0.5f - 0.5f, 0.f), 13.f);
        int iy0 = (int)floorf(cy); float wy = cy - (float)iy0; int iy1 = min(iy0 + 1, 13);
        float cx = fminf(fmaxf((xx + 0.5f) * 0.5f - 0.5f, 0.f), 13.f);
        int ix0 = (int)floorf(cx); float wx = cx - (float)ix0; int ix1 = min(ix0 + 1, 13);
        by0[tid] = iy0; by1[tid] = iy1; bwy[tid] = wy;
        bx0[tid] = ix0; bx1[tid] = ix1; bwx[tid] = wx;
    }

    // ---- load Q tile (transposed to [c][l]) ----
    const float* Qb = Qh + (size_t)b * PQ * CCH;
    for (int i = tid; i < 3072; i += 256) {
        int c4 = i % 96, l = i / 96;
        float4 v = make_float4(0.f, 0.f, 0.f, 0.f);
        if (l0 + l < PQ) v = *(const float4*)&Qb[(size_t)(l0 + l) * CCH + c4 * 4];
        int c = c4 * 4;
        Qs[(c + 0) * 36 + l] = v.x; Qs[(c + 1) * 36 + l] = v.y;
        Qs[(c + 2) * 36 + l] = v.z; Qs[(c + 3) * 36 + l] = v.w;
    }

    // ---- persistent softmax/AV state ----
    float m_run = -1e30f, s_run = 0.f;
    float acc[64];
    #pragma unroll
    for (int d = 0; d < 64; d++) acc[d] = 0.f;

    // D-phase unit mapping (SMSP-balanced): warps 0-3 wide (4x8), warps 4-7 narrow (4x4)
    int du = (tid < 128) ? 2 * tid : 128 + tid;
    int d_h = du >> 6;
    int d_r = du & 63;
    int d_l = (d_r >> 3) * 4;
    int d_t = (d_r & 7) * 4;
    // AV unit mapping: warps 0-3 full row (64 d), warps 4-7 half row (32 d)
    int au = (tid < 128) ? 2 * tid : 128 + tid;
    int a_o = au >> 6;
    int a_l = (au >> 1) & 31;
    int a_h = au & 1;      // 0 for wide threads

    const float* Kb = Kh + (size_t)b * PQ * CCH;
    const float* Vb = Vh + (size_t)b * PQ * CCH;
    const float* Rb = Rm + (size_t)b * HEADS * SS * TT;

    for (int t0 = 0; t0 < PQ; t0 += 32) {
        __syncthreads();   // prior-tile consumers of Ks/Vs/Ps done

        // ---- load K (transposed) and V tiles ----
        for (int i = tid; i < 3072; i += 256) {
            int c4 = i % 96, t = i / 96;
            int gt = t0 + t; int c = c4 * 4;
            float4 kv = make_float4(0.f, 0.f, 0.f, 0.f);
            float4 vv = make_float4(0.f, 0.f, 0.f, 0.f);
            if (gt < PQ) {
                kv = *(const float4*)&Kb[(size_t)gt * CCH + c];
                vv = *(const float4*)&Vb[(size_t)gt * CCH + c];
            }
            Ks[(c + 0) * 36 + t] = kv.x; Ks[(c + 1) * 36 + t] = kv.y;
            Ks[(c + 2) * 36 + t] = kv.z; Ks[(c + 3) * 36 + t] = kv.w;
            *(float4*)&Vs[t * 384 + c] = vv;
        }
        __syncthreads();

        // ---- D phase: raw per-head dots into Ps ----
        {
            const float* qp = Qs + (d_h * 64) * 36 + d_l;
            const float* kp = Ks + (d_h * 64) * 36 + d_t;
            if (tid < 128) {
                float da[4][8];
                #pragma unroll
                for (int i = 0; i < 4; i++)
                    #pragma unroll
                    for (int j = 0; j < 8; j++) da[i][j] = 0.f;
                #pragma unroll 4
                for (int cc = 0; cc < 64; cc++) {
                    float4 q  = *(const float4*)(qp + cc * 36);
                    float4 ka = *(const float4*)(kp + cc * 36);
                    float4 kb2 = *(const float4*)(kp + cc * 36 + 4);
                    float qv[4] = {q.x, q.y, q.z, q.w};
                    float kvv[8] = {ka.x, ka.y, ka.z, ka.w, kb2.x, kb2.y, kb2.z, kb2.w};
                    #pragma unroll
                    for (int i = 0; i < 4; i++)
                        #pragma unroll
                        for (int j = 0; j < 8; j++)
                            da[i][j] += qv[i] * kvv[j];
                }
                #pragma unroll
                for (int i = 0; i < 4; i++)
                    #pragma unroll
                    for (int j = 0; j < 8; j++)
                        Ps[d_h * 1056 + (d_l + i) * 33 + d_t + j] = da[i][j];
            } else {
                float da[4][4];
                #pragma unroll
                for (int i = 0; i < 4; i++)
                    #pragma unroll
                    for (int j = 0; j < 4; j++) da[i][j] = 0.f;
                #pragma unroll 4
                for (int cc = 0; cc < 64; cc++) {
                    float4 q  = *(const float4*)(qp + cc * 36);
                    float4 ka = *(const float4*)(kp + cc * 36);
                    float qv[4] = {q.x, q.y, q.z, q.w};
                    float kvv[4] = {ka.x, ka.y, ka.z, ka.w};
                    #pragma unroll
                    for (int i = 0; i < 4; i++)
                        #pragma unroll
                        for (int j = 0; j < 4; j++)
                            da[i][j] += qv[i] * kvv[j];
                }
                #pragma unroll
                for (int i = 0; i < 4; i++)
                    #pragma unroll
                    for (int j = 0; j < 4; j++)
                        Ps[d_h * 1056 + (d_l + i) * 33 + d_t + j] = da[i][j];
            }
        }
        __syncthreads();

        // ---- mix phase: P[o,l,t] = bias + sum_h wf*D + bilinear residual ----
        for (int e2 = tid; e2 < 1024; e2 += 256) {
            int l = e2 >> 5, t = e2 & 31;
            int gt = t0 + t;
            float dv[6];
            #pragma unroll
            for (int h = 0; h < 6; h++) dv[h] = Ps[h * 1056 + l * 33 + t];
            if (gt < PQ) {
                int yy0 = by0[l], yy1 = by1[l], xx0 = bx0[l], xx1 = bx1[l];
                float wy = bwy[l], wx = bwx[l];
                size_t o00 = (size_t)(yy0 * 14 + xx0) * TT;
                size_t o01 = (size_t)(yy0 * 14 + xx1) * TT;
                size_t o10 = (size_t)(yy1 * 14 + xx0) * TT;
                size_t o11 = (size_t)(yy1 * 14 + xx1) * TT;
                #pragma unroll
                for (int o = 0; o < 6; o++) {
                    const float* R = Rb + (size_t)o * SS * TT + gt;
                    float v00 = R[o00], v01 = R[o01], v10 = R[o10], v11 = R[o11];
                    float r0 = v00 + (v01 - v00) * wx;
                    float r1 = v10 + (v11 - v10) * wx;
                    float resid = r0 + (r1 - r0) * wy;
                    float pv = bfs[o] + resid;
                    #pragma unroll
                    for (int h = 0; h < 6; h++) pv += wfs[o][h] * dv[h];
                    Ps[o * 1056 + l * 33 + t] = pv;
                }
            } else {
                #pragma unroll
                for (int o = 0; o < 6; o++)
                    Ps[o * 1056 + l * 33 + t] = -1e30f;
            }
        }
        __syncthreads();

        // ---- online softmax + AV ----
        {
            const float* prow = Ps + a_o * 1056 + a_l * 33;
            float p[32];
            float tm = -1e30f;
            #pragma unroll
            for (int t = 0; t < 32; t++) { p[t] = prow[t]; tm = fmaxf(tm, p[t]); }
            float mnew = fmaxf(m_run, tm);
            float corr = __expf(m_run - mnew);
            m_run = mnew;
            float ssum = 0.f;
            #pragma unroll
            for (int t = 0; t < 32; t++) { p[t] = __expf(p[t] - mnew); ssum += p[t]; }
            s_run = s_run * corr + ssum;

            const float* vb2 = Vs + a_o * 64 + a_h * 32;
            if (tid < 128) {
                #pragma unroll
                for (int d = 0; d < 64; d++) acc[d] *= corr;
                #pragma unroll 2
                for (int t = 0; t < 32; t++) {
                    const float* vt = vb2 + t * 384;
                    float ev = p[t];
                    #pragma unroll
                    for (int d4 = 0; d4 < 16; d4++) {
                        float4 v = *(const float4*)(vt + d4 * 4);
                        acc[d4 * 4 + 0] += ev * v.x;
                        acc[d4 * 4 + 1] += ev * v.y;
                        acc[d4 * 4 + 2] += ev * v.z;
                        acc[d4 * 4 + 3] += ev * v.w;
                    }
                }
            } else {
                #pragma unroll
                for (int d = 0; d < 32; d++) acc[d] *= corr;
                #pragma unroll 2
                for (int t = 0; t < 32; t++) {
                    const float* vt = vb2 + t * 384;
                    float ev = p[t];
                    #pragma unroll
                    for (int d4 = 0; d4 < 8; d4++) {
                        float4 v = *(const float4*)(vt + d4 * 4);
                        acc[d4 * 4 + 0] += ev * v.x;
                        acc[d4 * 4 + 1] += ev * v.y;
                        acc[d4 * 4 + 2] += ev * v.z;
                        acc[d4 * 4 + 3] += ev * v.w;
                    }
                }
            }
        }
    }

    // ---- epilogue: normalize and write ----
    int gl = l0 + a_l;
    if (gl < PQ) {
        float inv = 1.f / s_run;
        float* op = AVo + ((size_t)b * PQ + gl) * CCH + a_o * 64 + a_h * 32;
        if (tid < 128) {
            #pragma unroll
            for (int d = 0; d < 64; d++) op[d] = acc[d] * inv;
        } else {
            #pragma unroll
            for (int d = 0; d < 32; d++) op[d] = acc[d] * inv;
        }
    }
}

// ---------------- launcher ----------------------------------------------------
extern "C" void kernel_launch(void* const* d_in, const int* in_sizes, int n_in,
                              void* d_out, int out_size)
{
    const float* x   = (const float*)d_in[0];
    const float* ra  = (const float*)d_in[1];
    const float* cw  = (const float*)d_in[2];
    const float* lng = (const float*)d_in[3];
    const float* lnb = (const float*)d_in[4];
    const float* wq  = (const float*)d_in[5];
    const float* wk  = (const float*)d_in[6];
    const float* wv  = (const float*)d_in[7];
    const float* wp  = (const float*)d_in[8];
    const float* bp  = (const float*)d_in[9];
    const float* wf  = (const float*)d_in[10];
    const float* bf  = (const float*)d_in[11];
    float* out = (float*)d_out;

    float *Qln, *KV, *Qh, *Kh, *Vh, *Rm, *AV;
    cudaGetSymbolAddress((void**)&Qln, g_Qln);
    cudaGetSymbolAddress((void**)&KV,  g_KV);
    cudaGetSymbolAddress((void**)&Qh,  g_Qh);
    cudaGetSymbolAddress((void**)&Kh,  g_Kh);
    cudaGetSymbolAddress((void**)&Vh,  g_Vh);
    cudaGetSymbolAddress((void**)&Rm,  g_Rm);
    cudaGetSymbolAddress((void**)&AV,  g_AV);

    // 1. conv+LN and pool
    prep_k<<<dim3(PQ, BATCH), CCH>>>(x, cw, lng, lnb, Qln, KV);

    // 2. Q/K/V projections (M=6272=49*128, N=384=3*128)
    const int M = BATCH * PQ;
    gemm2_k<<<dim3(3, 49), 256>>>(Qln, wq, nullptr, Qh, M, CCH);
    gemm2_k<<<dim3(3, 49), 256>>>(KV,  wk, nullptr, Kh, M, CCH);
    gemm2_k<<<dim3(3, 49), 256>>>(KV,  wv, nullptr, Vh, M, CCH);

    // 3. residual pre-mix
    rmix_k<<<dim3(SS, BATCH), 256>>>(ra, wf, Rm);

    // 4. fused flash attention (scores + mix + residual + softmax + AV)
    int smem = (384 * 36 * 2 + 32 * 384 + HEADS * 32 * 33) * (int)sizeof(float); // 185088
    cudaFuncSetAttribute(flash_k, cudaFuncAttributeMaxDynamicSharedMemorySize, smem);
    flash_k<<<dim3((PQ + 31) / 32, BATCH), 256, smem>>>(Qh, Kh, Vh, Rm, wf, bf, AV);

    // 5. output projection + bias -> d_out
    gemm2_k<<<dim3(3, 49), 256>>>(AV, wp, bp, out, M, CCH);
}

// round 3
// speedup vs baseline: 1.2303x; 1.0038x over previous
#include <cuda_runtime.h>
#include <cuda_bf16.h>
#include <cstdint>
#include <cstddef>

// Problem constants
#define BATCH   8
#define HH      56
#define WW      56
#define CCH     384
#define HEADS   6
#define DH      64
#define PQ      784        // 28*28 tokens after stride-2 / pool
#define SS      196        // 14*14 residual source grid
#define TT      784        // key count

// ---------------- scratch (device globals; no runtime allocation) -------------
__device__ float g_Qln[BATCH * PQ * CCH];
__device__ float g_KV [BATCH * PQ * CCH];
__device__ float g_Qh [BATCH * PQ * CCH];
__device__ float g_Kh [BATCH * PQ * CCH];
__device__ float g_Vh [BATCH * PQ * CCH];
__device__ float g_Rm [BATCH * HEADS * SS * TT];   // pre-mixed residual (29.5 MB)
__device__ float g_AV [BATCH * PQ * CCH];

// ---------------- kernel 1: depthwise conv (stride2,pad1) + LN, and 2x2 avgpool
__global__ void prep_k(const float* __restrict__ x, const float* __restrict__ cw,
                       const float* __restrict__ lng, const float* __restrict__ lnb,
                       float* __restrict__ Qln, float* __restrict__ KV)
{
    int p = blockIdx.x;          // 0..783
    int b = blockIdx.y;          // 0..7
    int c = threadIdx.x;         // 0..383
    int oy = p / 28, ox = p % 28;
    const float* xb = x + (size_t)b * (HH * WW) * CCH;

    float acc = 0.f;
    #pragma unroll
    for (int dy = 0; dy < 3; dy++) {
        int y = 2 * oy + dy - 1;
        if ((unsigned)y < (unsigned)HH) {
            #pragma unroll
            for (int dx = 0; dx < 3; dx++) {
                int xx = 2 * ox + dx - 1;
                if ((unsigned)xx < (unsigned)WW)
                    acc += xb[(size_t)(y * WW + xx) * CCH + c] * cw[c * 9 + dy * 3 + dx];
            }
        }
    }

    int py = 2 * oy, px = 2 * ox;
    float pv = 0.25f * (xb[(size_t)(py * WW + px) * CCH + c] +
                        xb[(size_t)(py * WW + px + 1) * CCH + c] +
                        xb[(size_t)((py + 1) * WW + px) * CCH + c] +
                        xb[(size_t)((py + 1) * WW + px + 1) * CCH + c]);
    KV[((size_t)b * PQ + p) * CCH + c] = pv;

    __shared__ float ssum[CCH];
    __shared__ float ssq [CCH];
    ssum[c] = acc; ssq[c] = acc * acc;
    __syncthreads();
    if (c < 128) { ssum[c] += ssum[c + 128] + ssum[c + 256];
                   ssq [c] += ssq [c + 128] + ssq [c + 256]; }
    __syncthreads();
    for (int s = 64; s > 0; s >>= 1) {
        if (c < s) { ssum[c] += ssum[c + s]; ssq[c] += ssq[c + s]; }
        __syncthreads();
    }
    float mu  = ssum[0] * (1.f / CCH);
    float var = ssq[0] * (1.f / CCH) - mu * mu;
    float inv = rsqrtf(var + 1e-5f);
    Qln[((size_t)b * PQ + p) * CCH + c] = (acc - mu) * inv * lng[c] + lnb[c];
}

// ---------------- kernel 2: 128x128-tile GEMM, C = A * W^T (+bias) -----------
// A[M][384] row-major, W[N][384] row-major. M multiple of 128, N multiple of 128.
__global__ void __launch_bounds__(256) gemm2_k(const float* __restrict__ A,
                                               const float* __restrict__ W,
                                               const float* __restrict__ bias,
                                               float* __restrict__ C, int M, int N)
{
    __shared__ float As[8][132];
    __shared__ float Bs[8][132];
    int m0 = blockIdx.y * 128, n0 = blockIdx.x * 128;
    int tid = threadIdx.x;
    int ty = tid >> 4, tx = tid & 15;
    int lr = tid >> 1, lk = (tid & 1) * 4;

    float accr[8][8];
    #pragma unroll
    for (int i = 0; i < 8; i++)
        #pragma unroll
        for (int j = 0; j < 8; j++) accr[i][j] = 0.f;

    for (int k0 = 0; k0 < CCH; k0 += 8) {
        float4 av = *(const float4*)&A[(size_t)(m0 + lr) * CCH + k0 + lk];
        float4 bv = *(const float4*)&W[(size_t)(n0 + lr) * CCH + k0 + lk];
        __syncthreads();
        As[lk + 0][lr] = av.x; As[lk + 1][lr] = av.y;
        As[lk + 2][lr] = av.z; As[lk + 3][lr] = av.w;
        Bs[lk + 0][lr] = bv.x; Bs[lk + 1][lr] = bv.y;
        Bs[lk + 2][lr] = bv.z; Bs[lk + 3][lr] = bv.w;
        __syncthreads();
        #pragma unroll
        for (int kk = 0; kk < 8; kk++) {
            float4 a0 = *(const float4*)&As[kk][ty * 8];
            float4 a1 = *(const float4*)&As[kk][ty * 8 + 4];
            float4 b0 = *(const float4*)&Bs[kk][tx * 8];
            float4 b1 = *(const float4*)&Bs[kk][tx * 8 + 4];
            float avv[8] = {a0.x, a0.y, a0.z, a0.w, a1.x, a1.y, a1.z, a1.w};
            float bvv[8] = {b0.x, b0.y, b0.z, b0.w, b1.x, b1.y, b1.z, b1.w};
            #pragma unroll
            for (int i = 0; i < 8; i++)
                #pragma unroll
                for (int j = 0; j < 8; j++)
                    accr[i][j] += avv[i] * bvv[j];
        }
    }
    #pragma unroll
    for (int i = 0; i < 8; i++) {
        int gm = m0 + ty * 8 + i;
        #pragma unroll
        for (int j = 0; j < 8; j++) {
            int gn = n0 + tx * 8 + j;
            float v = accr[i][j];
            if (bias != nullptr) v += bias[gn];
            C[(size_t)gm * N + gn] = v;
        }
    }
}

// ---------------- kernel 3: pre-mix residual over source heads ----------------
__global__ void rmix_k(const float* __restrict__ ra, const float* __restrict__ wf,
                       float* __restrict__ Rm)
{
    int s = blockIdx.x;   // 0..195
    int b = blockIdx.y;   // 0..7
    __shared__ float w[HEADS][HEADS];
    if (threadIdx.x < 36)
        w[threadIdx.x / 6][threadIdx.x % 6] = wf[(threadIdx.x / 6) * 12 + 6 + (threadIdx.x % 6)];
    __syncthreads();
    for (int t = threadIdx.x; t < TT; t += blockDim.x) {
        float r[HEADS];
        #pragma unroll
        for (int h = 0; h < HEADS; h++)
            r[h] = ra[(((size_t)b * HEADS + h) * SS + s) * TT + t];
        #pragma unroll
        for (int o = 0; o < HEADS; o++) {
            float v = 0.f;
            #pragma unroll
            for (int h = 0; h < HEADS; h++) v += w[o][h] * r[h];
            Rm[(((size_t)b * HEADS + o) * SS + s) * TT + t] = v;
        }
    }
}

// ---------------- kernel 4: fused flash attention -----------------------------
// One block per (b, 32-query tile). Streams 32-key K/V tiles.
// Per tile: D[h,l,t] (per-head dots) -> head-mix + bias + bilinear residual ->
// online softmax -> AV accumulation. Eliminates the P tensor entirely.
__global__ void __launch_bounds__(256) flash_k(
    const float* __restrict__ Qh, const float* __restrict__ Kh,
    const float* __restrict__ Vh, const float* __restrict__ Rm,
    const float* __restrict__ wf, const float* __restrict__ bf,
    float* __restrict__ AVo)
{
    extern __shared__ float sm[];
    float* Qs = sm;                         // [384][36]  (c-major, padded)
    float* Ks = Qs + 384 * 36;              // [384][36]
    float* Vs = Ks + 384 * 36;              // [32][384]  (t-major)
    float* Ps = Vs + 32 * 384;              // [6][32][33]
    __shared__ float wfs[HEADS][HEADS], bfs[HEADS];
    __shared__ int   by0[32], by1[32], bx0[32], bx1[32];
    __shared__ float bwy[32], bwx[32];

    int b  = blockIdx.y;
    int l0 = blockIdx.x * 32;
    int tid = threadIdx.x;
    const float scale = rsqrtf((float)CCH);

    if (tid < 36) wfs[tid / 6][tid % 6] = wf[(tid / 6) * 12 + (tid % 6)] * scale;
    if (tid < 6)  bfs[tid] = bf[tid];
    if (tid < 32) {
        int gl = min(l0 + tid, PQ - 1);
        int y = gl / 28, xx = gl % 28;
        float cy = fminf(fmaxf((y + 0.5f) * 0.5f - 0.5f, 0.f), 13.f);
        int iy0 = (int)floorf(cy); float wy = cy - (float)iy0; int iy1 = min(iy0 + 1, 13);
        float cx = fminf(fmaxf((xx + 0.5f) * 0.5f - 0.5f, 0.f), 13.f);
        int ix0 = (int)floorf(cx); float wx = cx - (float)ix0; int ix1 = min(ix0 + 1, 13);
        by0[tid] = iy0; by1[tid] = iy1; bwy[tid] = wy;
        bx0[tid] = ix0; bx1[tid] = ix1; bwx[tid] = wx;
    }

    // ---- load Q tile (transposed to [c][l]) ----
    const float* Qb = Qh + (size_t)b * PQ * CCH;
    for (int i = tid; i < 3072; i += 256) {
        int c4 = i % 96, l = i / 96;
        float4 v = make_float4(0.f, 0.f, 0.f, 0.f);
        if (l0 + l < PQ) v = *(const float4*)&Qb[(size_t)(l0 + l) * CCH + c4 * 4];
        int c = c4 * 4;
        Qs[(c + 0) * 36 + l] = v.x; Qs[(c + 1) * 36 + l] = v.y;
        Qs[(c + 2) * 36 + l] = v.z; Qs[(c + 3) * 36 + l] = v.w;
    }

    // ---- persistent softmax/AV state ----
    float m_run = -1e30f, s_run = 0.f;
    float acc[64];
    #pragma unroll
    for (int d = 0; d < 64; d++) acc[d] = 0.f;

    // D-phase unit mapping (SMSP-balanced): warps 0-3 wide (4x8), warps 4-7 narrow (4x4)
    int du = (tid < 128) ? 2 * tid : 128 + tid;
    int d_h = du >> 6;
    int d_r = du & 63;
    int d_l = (d_r >> 3) * 4;
    int d_t = (d_r & 7) * 4;
    // AV unit mapping: warps 0-3 full row (64 d), warps 4-7 half row (32 d)
    int au = (tid < 128) ? 2 * tid : 128 + tid;
    int a_o = au >> 6;
    int a_l = (au >> 1) & 31;
    int a_h = au & 1;      // 0 for wide threads

    const float* Kb = Kh + (size_t)b * PQ * CCH;
    const float* Vb = Vh + (size_t)b * PQ * CCH;
    const float* Rb = Rm + (size_t)b * HEADS * SS * TT;

    for (int t0 = 0; t0 < PQ; t0 += 32) {
        __syncthreads();   // prior-tile consumers of Ks/Vs/Ps done

        // ---- load K (transposed) and V tiles ----
        for (int i = tid; i < 3072; i += 256) {
            int c4 = i % 96, t = i / 96;
            int gt = t0 + t; int c = c4 * 4;
            float4 kv = make_float4(0.f, 0.f, 0.f, 0.f);
            float4 vv = make_float4(0.f, 0.f, 0.f, 0.f);
            if (gt < PQ) {
                kv = *(const float4*)&Kb[(size_t)gt * CCH + c];
                vv = *(const float4*)&Vb[(size_t)gt * CCH + c];
            }
            Ks[(c + 0) * 36 + t] = kv.x; Ks[(c + 1) * 36 + t] = kv.y;
            Ks[(c + 2) * 36 + t] = kv.z; Ks[(c + 3) * 36 + t] = kv.w;
            *(float4*)&Vs[t * 384 + c] = vv;
        }
        __syncthreads();

        // ---- D phase: raw per-head dots into Ps ----
        {
            const float* qp = Qs + (d_h * 64) * 36 + d_l;
            const float* kp = Ks + (d_h * 64) * 36 + d_t;
            if (tid < 128) {
                float da[4][8];
                #pragma unroll
                for (int i = 0; i < 4; i++)
                    #pragma unroll
                    for (int j = 0; j < 8; j++) da[i][j] = 0.f;
                #pragma unroll 4
                for (int cc = 0; cc < 64; cc++) {
                    float4 q  = *(const float4*)(qp + cc * 36);
                    float4 ka = *(const float4*)(kp + cc * 36);
                    float4 kb2 = *(const float4*)(kp + cc * 36 + 4);
                    float qv[4] = {q.x, q.y, q.z, q.w};
                    float kvv[8] = {ka.x, ka.y, ka.z, ka.w, kb2.x, kb2.y, kb2.z, kb2.w};
                    #pragma unroll
                    for (int i = 0; i < 4; i++)
                        #pragma unroll
                        for (int j = 0; j < 8; j++)
                            da[i][j] += qv[i] * kvv[j];
                }
                #pragma unroll
                for (int i = 0; i < 4; i++)
                    #pragma unroll
                    for (int j = 0; j < 8; j++)
                        Ps[d_h * 1056 + (d_l + i) * 33 + d_t + j] = da[i][j];
            } else {
                float da[4][4];
                #pragma unroll
                for (int i = 0; i < 4; i++)
                    #pragma unroll
                    for (int j = 0; j < 4; j++) da[i][j] = 0.f;
                #pragma unroll 4
                for (int cc = 0; cc < 64; cc++) {
                    float4 q  = *(const float4*)(qp + cc * 36);
                    float4 ka = *(const float4*)(kp + cc * 36);
                    float qv[4] = {q.x, q.y, q.z, q.w};
                    float kvv[4] = {ka.x, ka.y, ka.z, ka.w};
                    #pragma unroll
                    for (int i = 0; i < 4; i++)
                        #pragma unroll
                        for (int j = 0; j < 4; j++)
                            da[i][j] += qv[i] * kvv[j];
                }
                #pragma unroll
                for (int i = 0; i < 4; i++)
                    #pragma unroll
                    for (int j = 0; j < 4; j++)
                        Ps[d_h * 1056 + (d_l + i) * 33 + d_t + j] = da[i][j];
            }
        }
        __syncthreads();

        // ---- mix phase: P[o,l,t] = bias + sum_h wf*D + bilinear residual ----
        for (int e2 = tid; e2 < 1024; e2 += 256) {
            int l = e2 >> 5, t = e2 & 31;
            int gt = t0 + t;
            float dv[6];
            #pragma unroll
            for (int h = 0; h < 6; h++) dv[h] = Ps[h * 1056 + l * 33 + t];
            if (gt < PQ) {
                int yy0 = by0[l], yy1 = by1[l], xx0 = bx0[l], xx1 = bx1[l];
                float wy = bwy[l], wx = bwx[l];
                size_t o00 = (size_t)(yy0 * 14 + xx0) * TT;
                size_t o01 = (size_t)(yy0 * 14 + xx1) * TT;
                size_t o10 = (size_t)(yy1 * 14 + xx0) * TT;
                size_t o11 = (size_t)(yy1 * 14 + xx1) * TT;
                #pragma unroll
                for (int o = 0; o < 6; o++) {
                    const float* R = Rb + (size_t)o * SS * TT + gt;
                    float v00 = R[o00], v01 = R[o01], v10 = R[o10], v11 = R[o11];
                    float r0 = v00 + (v01 - v00) * wx;
                    float r1 = v10 + (v11 - v10) * wx;
                    float resid = r0 + (r1 - r0) * wy;
                    float pv = bfs[o] + resid;
                    #pragma unroll
                    for (int h = 0; h < 6; h++) pv += wfs[o][h] * dv[h];
                    Ps[o * 1056 + l * 33 + t] = pv;
                }
            } else {
                #pragma unroll
                for (int o = 0; o < 6; o++)
                    Ps[o * 1056 + l * 33 + t] = -1e30f;
            }
        }
        __syncthreads();

        // ---- online softmax + AV ----
        {
            const float* prow = Ps + a_o * 1056 + a_l * 33;
            float p[32];
            float tm = -1e30f;
            #pragma unroll
            for (int t = 0; t < 32; t++) { p[t] = prow[t]; tm = fmaxf(tm, p[t]); }
            float mnew = fmaxf(m_run, tm);
            float corr = __expf(m_run - mnew);
            m_run = mnew;
            float ssum = 0.f;
            #pragma unroll
            for (int t = 0; t < 32; t++) { p[t] = __expf(p[t] - mnew); ssum += p[t]; }
            s_run = s_run * corr + ssum;

            const float* vb2 = Vs + a_o * 64 + a_h * 32;
            if (tid < 128) {
                #pragma unroll
                for (int d = 0; d < 64; d++) acc[d] *= corr;
                #pragma unroll 2
                for (int t = 0; t < 32; t++) {
                    const float* vt = vb2 + t * 384;
                    float ev = p[t];
                    #pragma unroll
                    for (int d4 = 0; d4 < 16; d4++) {
                        float4 v = *(const float4*)(vt + d4 * 4);
                        acc[d4 * 4 + 0] += ev * v.x;
                        acc[d4 * 4 + 1] += ev * v.y;
                        acc[d4 * 4 + 2] += ev * v.z;
                        acc[d4 * 4 + 3] += ev * v.w;
                    }
                }
            } else {
                #pragma unroll
                for (int d = 0; d < 32; d++) acc[d] *= corr;
                #pragma unroll 2
                for (int t = 0; t < 32; t++) {
                    const float* vt = vb2 + t * 384;
                    float ev = p[t];
                    #pragma unroll
                    for (int d4 = 0; d4 < 8; d4++) {
                        float4 v = *(const float4*)(vt + d4 * 4);
                        acc[d4 * 4 + 0] += ev * v.x;
                        acc[d4 * 4 + 1] += ev * v.y;
                        acc[d4 * 4 + 2] += ev * v.z;
                        acc[d4 * 4 + 3] += ev * v.w;
                    }
                }
            }
        }
    }

    // ---- epilogue: normalize and write ----
    int gl = l0 + a_l;
    if (gl < PQ) {
        float inv = 1.f / s_run;
        float* op = AVo + ((size_t)b * PQ + gl) * CCH + a_o * 64 + a_h * 32;
        if (tid < 128) {
            #pragma unroll
            for (int d = 0; d < 64; d++) op[d] = acc[d] * inv;
        } else {
            #pragma unroll
            for (int d = 0; d < 32; d++) op[d] = acc[d] * inv;
        }
    }
}

// ---------------- launcher ----------------------------------------------------
extern "C" void kernel_launch(void* const* d_in, const int* in_sizes, int n_in,
                              void* d_out, int out_size)
{
    const float* x   = (const float*)d_in[0];
    const float* ra  = (const float*)d_in[1];
    const float* cw  = (const float*)d_in[2];
    const float* lng = (const float*)d_in[3];
    const float* lnb = (const float*)d_in[4];
    const float* wq  = (const float*)d_in[5];
    const float* wk  = (const float*)d_in[6];
    const float* wv  = (const float*)d_in[7];
    const float* wp  = (const float*)d_in[8];
    const float* bp  = (const float*)d_in[9];
    const float* wf  = (const float*)d_in[10];
    const float* bf  = (const float*)d_in[11];
    float* out = (float*)d_out;

    float *Qln, *KV, *Qh, *Kh, *Vh, *Rm, *AV;
    cudaGetSymbolAddress((void**)&Qln, g_Qln);
    cudaGetSymbolAddress((void**)&KV,  g_KV);
    cudaGetSymbolAddress((void**)&Qh,  g_Qh);
    cudaGetSymbolAddress((void**)&Kh,  g_Kh);
    cudaGetSymbolAddress((void**)&Vh,  g_Vh);
    cudaGetSymbolAddress((void**)&Rm,  g_Rm);
    cudaGetSymbolAddress((void**)&AV,  g_AV);

    // 1. conv+LN and pool
    prep_k<<<dim3(PQ, BATCH), CCH>>>(x, cw, lng, lnb, Qln, KV);

    // 2. Q/K/V projections (M=6272=49*128, N=384=3*128)
    const int M = BATCH * PQ;
    gemm2_k<<<dim3(3, 49), 256>>>(Qln, wq, nullptr, Qh, M, CCH);
    gemm2_k<<<dim3(3, 49), 256>>>(KV,  wk, nullptr, Kh, M, CCH);
    gemm2_k<<<dim3(3, 49), 256>>>(KV,  wv, nullptr, Vh, M, CCH);

    // 3. residual pre-mix
    rmix_k<<<dim3(SS, BATCH), 256>>>(ra, wf, Rm);

    // 4. fused flash attention (scores + mix + residual + softmax + AV)
    int smem = (384 * 36 * 2 + 32 * 384 + HEADS * 32 * 33) * (int)sizeof(float); // 185088
    cudaFuncSetAttribute(flash_k, cudaFuncAttributeMaxDynamicSharedMemorySize, smem);
    flash_k<<<dim3((PQ + 31) / 32, BATCH), 256, smem>>>(Qh, Kh, Vh, Rm, wf, bf, AV);

    // 5. output projection + bias -> d_out
    gemm2_k<<<dim3(3, 49), 256>>>(AV, wp, bp, out, M, CCH);
}

// round 7
// speedup vs baseline: 1.5056x; 1.2237x over previous
#include <cuda_runtime.h>
#include <cstdint>
#include <cstddef>

#define BATCH 8
#define HH 56
#define WW 56
#define CCH 384
#define HEADS 6
#define DH 64
#define PQ 784
#define SS 196
#define TT 784

__device__ float g_Qln[BATCH * PQ * CCH];
__device__ float g_KV [BATCH * PQ * CCH];
__device__ float g_Qh [BATCH * PQ * CCH];
__device__ float g_Kh [BATCH * PQ * CCH];
__device__ float g_Vh [BATCH * PQ * CCH];
__device__ float g_Rm [BATCH * HEADS * SS * TT];
__device__ float g_AV [BATCH * PQ * CCH];

// ---------------- mma.sync tf32 helpers ----------------
__device__ __forceinline__ uint32_t f2tf(float f) {
    uint32_t r; asm("cvt.rna.tf32.f32 %0, %1;" : "=r"(r) : "f"(f)); return r;
}
__device__ __forceinline__ void mma8(float* d, const uint32_t* a, uint32_t b0, uint32_t b1) {
    asm volatile("mma.sync.aligned.m16n8k8.row.col.f32.tf32.tf32.f32 "
        "{%0,%1,%2,%3}, {%4,%5,%6,%7}, {%8,%9}, {%0,%1,%2,%3};"
        : "+f"(d[0]), "+f"(d[1]), "+f"(d[2]), "+f"(d[3])
        : "r"(a[0]), "r"(a[1]), "r"(a[2]), "r"(a[3]), "r"(b0), "r"(b1));
}

// dynamic smem offsets (bytes)
#define OFF_QP 0            // [128][72] u32
#define OFF_KP 36864        // [128][72] u32
#define OFF_PP 73728        // [128][136] u32
#define OFF_VP 143360       // [128][72] u32
#define OFF_RM 180224       // redmax [2][128] f32
#define OFF_RS 181248       // redsum [2][128] f32
#define OFF_B0 182272
#define OFF_B1 182784
#define OFF_B2 183296
#define OFF_B3 183808
#define OFF_WXA 184320
#define OFF_WYA 184832
#define SMT 185344

// ---------------- kernel 1: depthwise conv + LN + 2x2 avgpool ----------------
__global__ void prep_k(const float* __restrict__ x, const float* __restrict__ cw,
                       const float* __restrict__ lng, const float* __restrict__ lnb,
                       float* __restrict__ Qln, float* __restrict__ KV)
{
    int p = blockIdx.x, b = blockIdx.y, c = threadIdx.x;
    int oy = p / 28, ox = p % 28;
    const float* xb = x + (size_t)b * (HH * WW) * CCH;
    float acc = 0.f;
    #pragma unroll
    for (int dy = 0; dy < 3; dy++) {
        int y = 2 * oy + dy - 1;
        if ((unsigned)y < (unsigned)HH) {
            #pragma unroll
            for (int dx = 0; dx < 3; dx++) {
                int xx = 2 * ox + dx - 1;
                if ((unsigned)xx < (unsigned)WW)
                    acc += xb[(size_t)(y * WW + xx) * CCH + c] * cw[c * 9 + dy * 3 + dx];
            }
        }
    }
    int py = 2 * oy, px = 2 * ox;
    float pv = 0.25f * (xb[(size_t)(py * WW + px) * CCH + c] +
                        xb[(size_t)(py * WW + px + 1) * CCH + c] +
                        xb[(size_t)((py + 1) * WW + px) * CCH + c] +
                        xb[(size_t)((py + 1) * WW + px + 1) * CCH + c]);
    KV[((size_t)b * PQ + p) * CCH + c] = pv;

    __shared__ float ssum[CCH], ssq[CCH];
    ssum[c] = acc; ssq[c] = acc * acc;
    __syncthreads();
    if (c < 128) { ssum[c] += ssum[c + 128] + ssum[c + 256];
                   ssq [c] += ssq [c + 128] + ssq [c + 256]; }
    __syncthreads();
    for (int s = 64; s > 0; s >>= 1) {
        if (c < s) { ssum[c] += ssum[c + s]; ssq[c] += ssq[c + s]; }
        __syncthreads();
    }
    float mu  = ssum[0] * (1.f / CCH);
    float var = ssq[0] * (1.f / CCH) - mu * mu;
    float inv = rsqrtf(var + 1e-5f);
    Qln[((size_t)b * PQ + p) * CCH + c] = (acc - mu) * inv * lng[c] + lnb[c];
}

// ---------------- kernel 2: 128x128 fp32 GEMM, C = A*W^T (+bias) -------------
__global__ void __launch_bounds__(256) gemm2_k(const float* __restrict__ A,
                                               const float* __restrict__ W,
                                               const float* __restrict__ bias,
                                               float* __restrict__ C, int M, int N)
{
    __shared__ float As[8][132];
    __shared__ float Bs[8][132];
    int m0 = blockIdx.y * 128, n0 = blockIdx.x * 128;
    int tid = threadIdx.x;
    int ty = tid >> 4, tx = tid & 15;
    int lr = tid >> 1, lk = (tid & 1) * 4;
    float accr[8][8];
    #pragma unroll
    for (int i = 0; i < 8; i++)
        #pragma unroll
        for (int j = 0; j < 8; j++) accr[i][j] = 0.f;
    for (int k0 = 0; k0 < CCH; k0 += 8) {
        float4 av = *(const float4*)&A[(size_t)(m0 + lr) * CCH + k0 + lk];
        float4 bv = *(const float4*)&W[(size_t)(n0 + lr) * CCH + k0 + lk];
        __syncthreads();
        As[lk + 0][lr] = av.x; As[lk + 1][lr] = av.y; As[lk + 2][lr] = av.z; As[lk + 3][lr] = av.w;
        Bs[lk + 0][lr] = bv.x; Bs[lk + 1][lr] = bv.y; Bs[lk + 2][lr] = bv.z; Bs[lk + 3][lr] = bv.w;
        __syncthreads();
        #pragma unroll
        for (int kk = 0; kk < 8; kk++) {
            float4 a0 = *(const float4*)&As[kk][ty * 8];
            float4 a1 = *(const float4*)&As[kk][ty * 8 + 4];
            float4 b0 = *(const float4*)&Bs[kk][tx * 8];
            float4 b1 = *(const float4*)&Bs[kk][tx * 8 + 4];
            float avv[8] = {a0.x, a0.y, a0.z, a0.w, a1.x, a1.y, a1.z, a1.w};
            float bvv[8] = {b0.x, b0.y, b0.z, b0.w, b1.x, b1.y, b1.z, b1.w};
            #pragma unroll
            for (int i = 0; i < 8; i++)
                #pragma unroll
                for (int j = 0; j < 8; j++)
                    accr[i][j] += avv[i] * bvv[j];
        }
    }
    #pragma unroll
    for (int i = 0; i < 8; i++) {
        int gm = m0 + ty * 8 + i;
        #pragma unroll
        for (int j = 0; j < 8; j++) {
            int gn = n0 + tx * 8 + j;
            float v = accr[i][j];
            if (bias != nullptr) v += bias[gn];
            C[(size_t)gm * N + gn] = v;
        }
    }
}

// ---------------- kernel 3: residual pre-mix over source heads ----------------
__global__ void rmix_k(const float* __restrict__ ra, const float* __restrict__ wf,
                       float* __restrict__ Rm)
{
    int s = blockIdx.x, b = blockIdx.y;
    __shared__ float w[HEADS][HEADS];
    if (threadIdx.x < 36)
        w[threadIdx.x / 6][threadIdx.x % 6] = wf[(threadIdx.x / 6) * 12 + 6 + (threadIdx.x % 6)];
    __syncthreads();
    for (int t = threadIdx.x; t < TT; t += blockDim.x) {
        float r[HEADS];
        #pragma unroll
        for (int h = 0; h < HEADS; h++)
            r[h] = ra[(((size_t)b * HEADS + h) * SS + s) * TT + t];
        #pragma unroll
        for (int o = 0; o < HEADS; o++) {
            float v = 0.f;
            #pragma unroll
            for (int h = 0; h < HEADS; h++) v += w[o][h] * r[h];
            Rm[(((size_t)b * HEADS + o) * SS + s) * TT + t] = v;
        }
    }
}

// ---------------- kernel 4: flash attention via mma.sync tf32 -----------------
// grid (7 q-tiles, 48 (b,o)), 256 thr = 8 warps in 4x2 (m,n).
__global__ void __launch_bounds__(256, 1)
flashmma_k(const float* __restrict__ Qh, const float* __restrict__ Kh,
           const float* __restrict__ Vh, const float* __restrict__ Rm,
           const float* __restrict__ wf, const float* __restrict__ bf,
           float* __restrict__ AVo)
{
    extern __shared__ char smc[];
    uint32_t* Qp = (uint32_t*)(smc + OFF_QP);
    uint32_t* Kp = (uint32_t*)(smc + OFF_KP);
    uint32_t* Pp = (uint32_t*)(smc + OFF_PP);
    uint32_t* Vp = (uint32_t*)(smc + OFF_VP);
    float* redmax = (float*)(smc + OFF_RM);
    float* redsum = (float*)(smc + OFF_RS);
    int*   sc00 = (int*)(smc + OFF_B0);
    int*   sc01 = (int*)(smc + OFF_B1);
    int*   sc10 = (int*)(smc + OFF_B2);
    int*   sc11 = (int*)(smc + OFF_B3);
    float* swx  = (float*)(smc + OFF_WXA);
    float* swy  = (float*)(smc + OFF_WYA);
    __shared__ float qscs[8];

    int tid = threadIdx.x, wid = tid >> 5, lane = tid & 31;
    int g = lane >> 2, tg = lane & 3;
    int wm = wid & 3, wn = wid >> 2;
    int rm = wm * 32;
    int bo = blockIdx.y, b = bo / HEADS, o = bo % HEADS;
    int l0 = blockIdx.x * 128;

    const float scale = rsqrtf((float)CCH);
    if (tid < 6) qscs[tid] = wf[o * 12 + tid] * scale;
    if (tid == 6) qscs[6] = bf[o];
    if (tid < 128) {
        int pl = min(l0 + tid, PQ - 1);
        int y = pl / 28, xx = pl % 28;
        float cy = fminf(fmaxf(y * 0.5f - 0.25f, 0.f), 13.f);
        int iy0 = (int)cy; float wy = cy - (float)iy0; int iy1 = min(iy0 + 1, 13);
        float cx = fminf(fmaxf(xx * 0.5f - 0.25f, 0.f), 13.f);
        int ix0 = (int)cx; float wx = cx - (float)ix0; int ix1 = min(ix0 + 1, 13);
        sc00[tid] = (iy0 * 14 + ix0) * TT;
        sc01[tid] = (iy0 * 14 + ix1) * TT;
        sc10[tid] = (iy1 * 14 + ix0) * TT;
        sc11[tid] = (iy1 * 14 + ix1) * TT;
        swx[tid] = wx; swy[tid] = wy;
    }
    __syncthreads();
    const float biasv = qscs[6];

    const float* Qb = Qh + (size_t)b * PQ * CCH;
    const float* Kb = Kh + (size_t)b * PQ * CCH;
    const float* Vb = Vh + (size_t)b * PQ * CCH + o * DH;
    const float* Ro = Rm + (size_t)bo * SS * TT;

    float m_run[4], s_run[4];
    float av[2][4][4];
    #pragma unroll
    for (int i = 0; i < 4; i++) { m_run[i] = -1e30f; s_run[i] = 0.f; }
    #pragma unroll
    for (int a = 0; a < 2; a++)
        #pragma unroll
        for (int n = 0; n < 4; n++)
            #pragma unroll
            for (int c = 0; c < 4; c++) av[a][n][c] = 0.f;

    for (int kt = 0; kt < 7; kt++) {
        int t0 = kt * 128;
        float sacc[2][8][4];
        #pragma unroll
        for (int a = 0; a < 2; a++)
            #pragma unroll
            for (int n = 0; n < 8; n++)
                #pragma unroll
                for (int c = 0; c < 4; c++) sacc[a][n][c] = 0.f;

        // ===== QK^T over 6 c-chunks of 64 =====
        for (int cc = 0; cc < 6; cc++) {
            int c0 = cc * 64;
            float wqv = qscs[cc];
            __syncthreads();
            for (int idx = tid; idx < 2048; idx += 256) {
                int row = idx >> 4, cl = (idx & 15) * 4;
                float4 qv = make_float4(0.f, 0.f, 0.f, 0.f);
                float4 kv = make_float4(0.f, 0.f, 0.f, 0.f);
                if (l0 + row < PQ) qv = *(const float4*)&Qb[(size_t)(l0 + row) * CCH + c0 + cl];
                if (t0 + row < PQ) kv = *(const float4*)&Kb[(size_t)(t0 + row) * CCH + c0 + cl];
                uint4 qi, ki;
                qi.x = f2tf(qv.x * wqv); qi.y = f2tf(qv.y * wqv);
                qi.z = f2tf(qv.z * wqv); qi.w = f2tf(qv.w * wqv);
                ki.x = f2tf(kv.x); ki.y = f2tf(kv.y); ki.z = f2tf(kv.z); ki.w = f2tf(kv.w);
                *(uint4*)&Qp[row * 72 + cl] = qi;
                *(uint4*)&Kp[row * 72 + cl] = ki;
            }
            __syncthreads();
            #pragma unroll
            for (int k = 0; k < 8; k++) {
                int kc = k * 8;
                uint32_t af[2][4];
                #pragma unroll
                for (int mt = 0; mt < 2; mt++) {
                    int r0 = (rm + mt * 16 + g) * 72 + kc + tg;
                    af[mt][0] = Qp[r0];
                    af[mt][1] = Qp[r0 + 8 * 72];
                    af[mt][2] = Qp[r0 + 4];
                    af[mt][3] = Qp[r0 + 8 * 72 + 4];
                }
                #pragma unroll
                for (int nt = 0; nt < 8; nt++) {
                    int cn = wn * 64 + nt * 8;
                    uint32_t b0 = Kp[(cn + g) * 72 + kc + tg];
                    uint32_t b1 = Kp[(cn + g) * 72 + kc + tg + 4];
                    mma8(sacc[0][nt], af[0], b0, b1);
                    mma8(sacc[1][nt], af[1], b0, b1);
                }
            }
        }

        // ===== bias + bilinear residual + mask, row max =====
        float rmax[4] = {-1e30f, -1e30f, -1e30f, -1e30f};
        #pragma unroll
        for (int mt = 0; mt < 2; mt++)
        #pragma unroll
        for (int half = 0; half < 2; half++) {
            int lr = rm + mt * 16 + g + half * 8;
            int o00 = sc00[lr], o01 = sc01[lr], o10 = sc10[lr], o11 = sc11[lr];
            float wx = swx[lr], wy = swy[lr];
            int hr = mt * 2 + half;
            #pragma unroll
            for (int nt = 0; nt < 8; nt++) {
                int gt = t0 + wn * 64 + nt * 8 + 2 * tg;
                float v0, v1;
                if (gt < PQ) {
                    float2 p00 = *(const float2*)&Ro[o00 + gt];
                    float2 p01 = *(const float2*)&Ro[o01 + gt];
                    float2 p10 = *(const float2*)&Ro[o10 + gt];
                    float2 p11 = *(const float2*)&Ro[o11 + gt];
                    float r0x = p00.x + (p01.x - p00.x) * wx;
                    float r1x = p10.x + (p11.x - p10.x) * wx;
                    float r0y = p00.y + (p01.y - p00.y) * wx;
                    float r1y = p10.y + (p11.y - p10.y) * wx;
                    v0 = sacc[mt][nt][half * 2 + 0] + biasv + r0x + (r1x - r0x) * wy;
                    v1 = sacc[mt][nt][half * 2 + 1] + biasv + r0y + (r1y - r0y) * wy;
                } else { v0 = -1e30f; v1 = -1e30f; }
                sacc[mt][nt][half * 2 + 0] = v0;
                sacc[mt][nt][half * 2 + 1] = v1;
                rmax[hr] = fmaxf(rmax[hr], fmaxf(v0, v1));
            }
        }
        #pragma unroll
        for (int hr = 0; hr < 4; hr++) {
            rmax[hr] = fmaxf(rmax[hr], __shfl_xor_sync(0xffffffffu, rmax[hr], 1));
            rmax[hr] = fmaxf(rmax[hr], __shfl_xor_sync(0xffffffffu, rmax[hr], 2));
        }
        if (tg == 0) {
            #pragma unroll
            for (int hr = 0; hr < 4; hr++)
                redmax[wn * 128 + rm + (hr >> 1) * 16 + g + (hr & 1) * 8] = rmax[hr];
        }
        __syncthreads();

        float corr[4], mnew[4];
        #pragma unroll
        for (int hr = 0; hr < 4; hr++) {
            int lr = rm + (hr >> 1) * 16 + g + (hr & 1) * 8;
            float mt2 = fmaxf(redmax[lr], redmax[128 + lr]);
            mnew[hr] = fmaxf(m_run[hr], mt2);
            corr[hr] = __expf(m_run[hr] - mnew[hr]);
            m_run[hr] = mnew[hr];
        }
        float psum[4] = {0.f, 0.f, 0.f, 0.f};
        #pragma unroll
        for (int mt = 0; mt < 2; mt++)
            #pragma unroll
            for (int nt = 0; nt < 8; nt++)
                #pragma unroll
                for (int c = 0; c < 4; c++) {
                    int hr = mt * 2 + (c >> 1);
                    float e = __expf(sacc[mt][nt][c] - mnew[hr]);
                    sacc[mt][nt][c] = e;
                    psum[hr] += e;
                }
        #pragma unroll
        for (int hr = 0; hr < 4; hr++) {
            psum[hr] += __shfl_xor_sync(0xffffffffu, psum[hr], 1);
            psum[hr] += __shfl_xor_sync(0xffffffffu, psum[hr], 2);
        }
        if (tg == 0) {
            #pragma unroll
            for (int hr = 0; hr < 4; hr++)
                redsum[wn * 128 + rm + (hr >> 1) * 16 + g + (hr & 1) * 8] = psum[hr];
        }
        __syncthreads();
        #pragma unroll
        for (int hr = 0; hr < 4; hr++) {
            int lr = rm + (hr >> 1) * 16 + g + (hr & 1) * 8;
            s_run[hr] = s_run[hr] * corr[hr] + redsum[lr] + redsum[128 + lr];
        }
        // rescale AV accumulators
        #pragma unroll
        for (int mt = 0; mt < 2; mt++)
            #pragma unroll
            for (int nt = 0; nt < 4; nt++)
                #pragma unroll
                for (int c = 0; c < 4; c++)
                    av[mt][nt][c] *= corr[mt * 2 + (c >> 1)];

        // ===== store P (tf32) to smem =====
        #pragma unroll
        for (int mt = 0; mt < 2; mt++)
        #pragma unroll
        for (int half = 0; half < 2; half++) {
            int lr = rm + mt * 16 + g + half * 8;
            #pragma unroll
            for (int nt = 0; nt < 8; nt++) {
                uint2 pv;
                pv.x = f2tf(sacc[mt][nt][half * 2 + 0]);
                pv.y = f2tf(sacc[mt][nt][half * 2 + 1]);
                *(uint2*)&Pp[lr * 136 + wn * 64 + nt * 8 + 2 * tg] = pv;
            }
        }
        // ===== V fill =====
        for (int idx = tid; idx < 2048; idx += 256) {
            int row = idx >> 4, dl = (idx & 15) * 4;
            float4 vv = make_float4(0.f, 0.f, 0.f, 0.f);
            if (t0 + row < PQ) vv = *(const float4*)&Vb[(size_t)(t0 + row) * CCH + dl];
            uint4 vi;
            vi.x = f2tf(vv.x); vi.y = f2tf(vv.y); vi.z = f2tf(vv.z); vi.w = f2tf(vv.w);
            *(uint4*)&Vp[row * 72 + dl] = vi;
        }
        __syncthreads();

        // ===== AV += P * V (16 k-steps over 128 t) =====
        #pragma unroll
        for (int k = 0; k < 16; k++) {
            int kc = k * 8;
            uint32_t af[2][4];
            #pragma unroll
            for (int mt = 0; mt < 2; mt++) {
                int r0 = (rm + mt * 16 + g) * 136 + kc + tg;
                af[mt][0] = Pp[r0];
                af[mt][1] = Pp[r0 + 8 * 136];
                af[mt][2] = Pp[r0 + 4];
                af[mt][3] = Pp[r0 + 8 * 136 + 4];
            }
            #pragma unroll
            for (int nt = 0; nt < 4; nt++) {
                int cn = wn * 32 + nt * 8;
                uint32_t b0 = Vp[(kc + tg) * 72 + cn + g];
                uint32_t b1 = Vp[(kc + tg + 4) * 72 + cn + g];
                mma8(av[0][nt], af[0], b0, b1);
                mma8(av[1][nt], af[1], b0, b1);
            }
        }
    }

    // ===== epilogue =====
    float inv[4];
    #pragma unroll
    for (int hr = 0; hr < 4; hr++) inv[hr] = 1.f / s_run[hr];
    #pragma unroll
    for (int mt = 0; mt < 2; mt++)
    #pragma unroll
    for (int half = 0; half < 2; half++) {
        int gl = l0 + rm + mt * 16 + g + half * 8;
        if (gl < PQ) {
            int hr = mt * 2 + half;
            float* op = AVo + ((size_t)b * PQ + gl) * CCH + o * DH + wn * 32;
            #pragma unroll
            for (int nt = 0; nt < 4; nt++) {
                float2 w2;
                w2.x = av[mt][nt][half * 2 + 0] * inv[hr];
                w2.y = av[mt][nt][half * 2 + 1] * inv[hr];
                *(float2*)&op[nt * 8 + 2 * tg] = w2;
            }
        }
    }
}

// ---------------- launcher ----------------------------------------------------
extern "C" void kernel_launch(void* const* d_in, const int* in_sizes, int n_in,
                              void* d_out, int out_size)
{
    const float* x   = (const float*)d_in[0];
    const float* ra  = (const float*)d_in[1];
    const float* cw  = (const float*)d_in[2];
    const float* lng = (const float*)d_in[3];
    const float* lnb = (const float*)d_in[4];
    const float* wq  = (const float*)d_in[5];
    const float* wk  = (const float*)d_in[6];
    const float* wv  = (const float*)d_in[7];
    const float* wp  = (const float*)d_in[8];
    const float* bp  = (const float*)d_in[9];
    const float* wf  = (const float*)d_in[10];
    const float* bf  = (const float*)d_in[11];
    float* out = (float*)d_out;

    float *Qln, *KV, *Qh, *Kh, *Vh, *Rm, *AV;
    cudaGetSymbolAddress((void**)&Qln, g_Qln);
    cudaGetSymbolAddress((void**)&KV,  g_KV);
    cudaGetSymbolAddress((void**)&Qh,  g_Qh);
    cudaGetSymbolAddress((void**)&Kh,  g_Kh);
    cudaGetSymbolAddress((void**)&Vh,  g_Vh);
    cudaGetSymbolAddress((void**)&Rm,  g_Rm);
    cudaGetSymbolAddress((void**)&AV,  g_AV);

    prep_k<<<dim3(PQ, BATCH), CCH>>>(x, cw, lng, lnb, Qln, KV);

    const int M = BATCH * PQ;
    gemm2_k<<<dim3(3, 49), 256>>>(Qln, wq, nullptr, Qh, M, CCH);
    gemm2_k<<<dim3(3, 49), 256>>>(KV,  wk, nullptr, Kh, M, CCH);
    gemm2_k<<<dim3(3, 49), 256>>>(KV,  wv, nullptr, Vh, M, CCH);

    rmix_k<<<dim3(SS, BATCH), 256>>>(ra, wf, Rm);

    cudaFuncSetAttribute(flashmma_k, cudaFuncAttributeMaxDynamicSharedMemorySize, SMT);
    flashmma_k<<<dim3(7, BATCH * HEADS), 256, SMT>>>(Qh, Kh, Vh, Rm, wf, bf, AV);

    gemm2_k<<<dim3(3, 49), 256>>>(AV, wp, bp, out, M, CCH);
}

// round 10
// speedup vs baseline: 2.5120x; 1.6685x over previous
#include <cuda_runtime.h>
#include <cstdint>
#include <cstddef>

#define BATCH 8
#define HH 56
#define WW 56
#define CCH 384
#define HEADS 6
#define DH 64
#define PQ 784
#define SS 196
#define TT 784

__device__ float g_Qln[BATCH * PQ * CCH];
__device__ float g_KV [BATCH * PQ * CCH];
__device__ float g_Qh [BATCH * PQ * CCH];
__device__ float g_Kh [BATCH * PQ * CCH];
__device__ float g_Vh [BATCH * PQ * CCH];
__device__ float g_Rm [BATCH * HEADS * SS * TT];
__device__ float g_AV [BATCH * PQ * CCH];

// ---------------- mma helpers ----------------
__device__ __forceinline__ uint32_t f2tf(float f) {
    uint32_t r; asm("cvt.rna.tf32.f32 %0, %1;" : "=r"(r) : "f"(f)); return r;
}
__device__ __forceinline__ uint32_t bf2(float lo, float hi) {
    uint32_t r; asm("cvt.rn.bf16x2.f32 %0, %1, %2;" : "=r"(r) : "f"(hi), "f"(lo)); return r;
}
__device__ __forceinline__ void mma8(float* d, const uint32_t* a, uint32_t b0, uint32_t b1) {
    asm volatile("mma.sync.aligned.m16n8k8.row.col.f32.tf32.tf32.f32 "
        "{%0,%1,%2,%3}, {%4,%5,%6,%7}, {%8,%9}, {%0,%1,%2,%3};"
        : "+f"(d[0]), "+f"(d[1]), "+f"(d[2]), "+f"(d[3])
        : "r"(a[0]), "r"(a[1]), "r"(a[2]), "r"(a[3]), "r"(b0), "r"(b1));
}
__device__ __forceinline__ void mma16(float* d, const uint32_t* a, uint32_t b0, uint32_t b1) {
    asm volatile("mma.sync.aligned.m16n8k16.row.col.f32.bf16.bf16.f32 "
        "{%0,%1,%2,%3}, {%4,%5,%6,%7}, {%8,%9}, {%0,%1,%2,%3};"
        : "+f"(d[0]), "+f"(d[1]), "+f"(d[2]), "+f"(d[3])
        : "r"(a[0]), "r"(a[1]), "r"(a[2]), "r"(a[3]), "r"(b0), "r"(b1));
}

// flash smem map (bytes). Q resident bf16 (stride 196 u32). K chunk bf16 (stride 68).
// P tf32 (stride 132) aliases K region (phase-disjoint). V tf32 (stride 72) disjoint.
#define OFF_Q   0
#define OFF_K   100352
#define OFF_P   100352
#define OFF_V   167936
#define OFF_RM  204800
#define OFF_RS  205824
#define OFF_B0  206848
#define OFF_B1  207360
#define OFF_B2  207872
#define OFF_B3  208384
#define OFF_WXA 208896
#define OFF_WYA 209408
#define SMT     209920

// gemm_tc smem
#define GOFF_A 0
#define GOFF_B 67584
#define GSMT   135168

// ---------------- kernel 1: depthwise conv + LN + 2x2 avgpool ----------------
__global__ void prep_k(const float* __restrict__ x, const float* __restrict__ cw,
                       const float* __restrict__ lng, const float* __restrict__ lnb,
                       float* __restrict__ Qln, float* __restrict__ KV)
{
    int p = blockIdx.x, b = blockIdx.y, c = threadIdx.x;
    int oy = p / 28, ox = p % 28;
    const float* xb = x + (size_t)b * (HH * WW) * CCH;
    float acc = 0.f;
    #pragma unroll
    for (int dy = 0; dy < 3; dy++) {
        int y = 2 * oy + dy - 1;
        if ((unsigned)y < (unsigned)HH) {
            #pragma unroll
            for (int dx = 0; dx < 3; dx++) {
                int xx = 2 * ox + dx - 1;
                if ((unsigned)xx < (unsigned)WW)
                    acc += xb[(size_t)(y * WW + xx) * CCH + c] * cw[c * 9 + dy * 3 + dx];
            }
        }
    }
    int py = 2 * oy, px = 2 * ox;
    float pv = 0.25f * (xb[(size_t)(py * WW + px) * CCH + c] +
                        xb[(size_t)(py * WW + px + 1) * CCH + c] +
                        xb[(size_t)((py + 1) * WW + px) * CCH + c] +
                        xb[(size_t)((py + 1) * WW + px + 1) * CCH + c]);
    KV[((size_t)b * PQ + p) * CCH + c] = pv;

    __shared__ float ssum[CCH], ssq[CCH];
    ssum[c] = acc; ssq[c] = acc * acc;
    __syncthreads();
    if (c < 128) { ssum[c] += ssum[c + 128] + ssum[c + 256];
                   ssq [c] += ssq [c + 128] + ssq [c + 256]; }
    __syncthreads();
    for (int s = 64; s > 0; s >>= 1) {
        if (c < s) { ssum[c] += ssum[c + s]; ssq[c] += ssq[c + s]; }
        __syncthreads();
    }
    float mu  = ssum[0] * (1.f / CCH);
    float var = ssq[0] * (1.f / CCH) - mu * mu;
    float inv = rsqrtf(var + 1e-5f);
    Qln[((size_t)b * PQ + p) * CCH + c] = (acc - mu) * inv * lng[c] + lnb[c];
}

// ---------------- kernel 2a: tf32 tensor GEMM, C = A*W^T (+bias) -------------
// blocks 128x128, 8 warps (4x2), warp tile 32x64.
__global__ void __launch_bounds__(256, 1) gemm_tc(const float* __restrict__ A,
                                                  const float* __restrict__ W,
                                                  const float* __restrict__ bias,
                                                  float* __restrict__ C, int M, int N)
{
    extern __shared__ char smc[];
    uint32_t* Ap = (uint32_t*)(smc + GOFF_A);   // [128][132]
    uint32_t* Bp = (uint32_t*)(smc + GOFF_B);   // [128][132]
    int tid = threadIdx.x, wid = tid >> 5, lane = tid & 31;
    int g = lane >> 2, tg = lane & 3;
    int wm = wid & 3, wn = wid >> 2;
    int rm = wm * 32;
    int m0 = blockIdx.y * 128, n0 = blockIdx.x * 128;

    float acc[2][8][4];
    #pragma unroll
    for (int a = 0; a < 2; a++)
        #pragma unroll
        for (int n = 0; n < 8; n++)
            #pragma unroll
            for (int c = 0; c < 4; c++) acc[a][n][c] = 0.f;

    for (int k0 = 0; k0 < CCH; k0 += 128) {
        __syncthreads();
        for (int idx = tid; idx < 4096; idx += 256) {
            int row = idx >> 5, cl = (idx & 31) * 4;
            float4 av = *(const float4*)&A[(size_t)(m0 + row) * CCH + k0 + cl];
            float4 wv = *(const float4*)&W[(size_t)(n0 + row) * CCH + k0 + cl];
            uint4 ai, wi;
            ai.x = f2tf(av.x); ai.y = f2tf(av.y); ai.z = f2tf(av.z); ai.w = f2tf(av.w);
            wi.x = f2tf(wv.x); wi.y = f2tf(wv.y); wi.z = f2tf(wv.z); wi.w = f2tf(wv.w);
            *(uint4*)&Ap[row * 132 + cl] = ai;
            *(uint4*)&Bp[row * 132 + cl] = wi;
        }
        __syncthreads();
        #pragma unroll
        for (int ks = 0; ks < 16; ks++) {
            int kc = ks * 8;
            uint32_t af[2][4];
            #pragma unroll
            for (int mt = 0; mt < 2; mt++) {
                int r0 = (rm + mt * 16 + g) * 132 + kc + tg;
                af[mt][0] = Ap[r0];
                af[mt][1] = Ap[r0 + 8 * 132];
                af[mt][2] = Ap[r0 + 4];
                af[mt][3] = Ap[r0 + 8 * 132 + 4];
            }
            #pragma unroll
            for (int nt = 0; nt < 8; nt++) {
                int cn = wn * 64 + nt * 8;
                uint32_t b0 = Bp[(cn + g) * 132 + kc + tg];
                uint32_t b1 = Bp[(cn + g) * 132 + kc + tg + 4];
                mma8(acc[0][nt], af[0], b0, b1);
                mma8(acc[1][nt], af[1], b0, b1);
            }
        }
    }
    #pragma unroll
    for (int mt = 0; mt < 2; mt++)
    #pragma unroll
    for (int half = 0; half < 2; half++) {
        int gm = m0 + rm + mt * 16 + g + half * 8;
        #pragma unroll
        for (int nt = 0; nt < 8; nt++) {
            int gn = n0 + wn * 64 + nt * 8 + 2 * tg;
            float2 w2;
            w2.x = acc[mt][nt][half * 2 + 0];
            w2.y = acc[mt][nt][half * 2 + 1];
            if (bias != nullptr) { w2.x += bias[gn]; w2.y += bias[gn + 1]; }
            *(float2*)&C[(size_t)gm * N + gn] = w2;
        }
    }
}

// ---------------- kernel 2b: 128x128 fp32 GEMM (out-projection) --------------
__global__ void __launch_bounds__(256) gemm2_k(const float* __restrict__ A,
                                               const float* __restrict__ W,
                                               const float* __restrict__ bias,
                                               float* __restrict__ C, int M, int N)
{
    __shared__ float As[8][132];
    __shared__ float Bs[8][132];
    int m0 = blockIdx.y * 128, n0 = blockIdx.x * 128;
    int tid = threadIdx.x;
    int ty = tid >> 4, tx = tid & 15;
    int lr = tid >> 1, lk = (tid & 1) * 4;
    float accr[8][8];
    #pragma unroll
    for (int i = 0; i < 8; i++)
        #pragma unroll
        for (int j = 0; j < 8; j++) accr[i][j] = 0.f;
    for (int k0 = 0; k0 < CCH; k0 += 8) {
        float4 av = *(const float4*)&A[(size_t)(m0 + lr) * CCH + k0 + lk];
        float4 bv = *(const float4*)&W[(size_t)(n0 + lr) * CCH + k0 + lk];
        __syncthreads();
        As[lk + 0][lr] = av.x; As[lk + 1][lr] = av.y; As[lk + 2][lr] = av.z; As[lk + 3][lr] = av.w;
        Bs[lk + 0][lr] = bv.x; Bs[lk + 1][lr] = bv.y; Bs[lk + 2][lr] = bv.z; Bs[lk + 3][lr] = bv.w;
        __syncthreads();
        #pragma unroll
        for (int kk = 0; kk < 8; kk++) {
            float4 a0 = *(const float4*)&As[kk][ty * 8];
            float4 a1 = *(const float4*)&As[kk][ty * 8 + 4];
            float4 b0 = *(const float4*)&Bs[kk][tx * 8];
            float4 b1 = *(const float4*)&Bs[kk][tx * 8 + 4];
            float avv[8] = {a0.x, a0.y, a0.z, a0.w, a1.x, a1.y, a1.z, a1.w};
            float bvv[8] = {b0.x, b0.y, b0.z, b0.w, b1.x, b1.y, b1.z, b1.w};
            #pragma unroll
            for (int i = 0; i < 8; i++)
                #pragma unroll
                for (int j = 0; j < 8; j++)
                    accr[i][j] += avv[i] * bvv[j];
        }
    }
    #pragma unroll
    for (int i = 0; i < 8; i++) {
        int gm = m0 + ty * 8 + i;
        #pragma unroll
        for (int j = 0; j < 8; j++) {
            int gn = n0 + tx * 8 + j;
            float v = accr[i][j];
            if (bias != nullptr) v += bias[gn];
            C[(size_t)gm * N + gn] = v;
        }
    }
}

// ---------------- kernel 3: residual pre-mix over source heads ----------------
__global__ void rmix_k(const float* __restrict__ ra, const float* __restrict__ wf,
                       float* __restrict__ Rm)
{
    int s = blockIdx.x, b = blockIdx.y;
    __shared__ float w[HEADS][HEADS];
    if (threadIdx.x < 36)
        w[threadIdx.x / 6][threadIdx.x % 6] = wf[(threadIdx.x / 6) * 12 + 6 + (threadIdx.x % 6)];
    __syncthreads();
    for (int t = threadIdx.x; t < TT; t += blockDim.x) {
        float r[HEADS];
        #pragma unroll
        for (int h = 0; h < HEADS; h++)
            r[h] = ra[(((size_t)b * HEADS + h) * SS + s) * TT + t];
        #pragma unroll
        for (int o = 0; o < HEADS; o++) {
            float v = 0.f;
            #pragma unroll
            for (int h = 0; h < HEADS; h++) v += w[o][h] * r[h];
            Rm[(((size_t)b * HEADS + o) * SS + s) * TT + t] = v;
        }
    }
}

// ---------------- kernel 4: flash attention (bf16 QK + tf32 PV) ---------------
// grid (7 q-tiles, 48 (b,o)), 256 thr = 8 warps (4x2). Q' resident in smem.
__global__ void __launch_bounds__(256, 1)
flashmma_k(const float* __restrict__ Qh, const float* __restrict__ Kh,
           const float* __restrict__ Vh, const float* __restrict__ Rm,
           const float* __restrict__ wf, const float* __restrict__ bf,
           float* __restrict__ AVo)
{
    extern __shared__ char smc[];
    uint32_t* Qp = (uint32_t*)(smc + OFF_Q);   // bf16x2, row stride 196 u32
    uint32_t* Kp = (uint32_t*)(smc + OFF_K);   // bf16x2, row stride 68 u32
    uint32_t* Pp = (uint32_t*)(smc + OFF_P);   // tf32,   row stride 132 u32
    uint32_t* Vp = (uint32_t*)(smc + OFF_V);   // tf32,   row stride 72 u32
    float* redmax = (float*)(smc + OFF_RM);
    float* redsum = (float*)(smc + OFF_RS);
    int*   sc00 = (int*)(smc + OFF_B0);
    int*   sc01 = (int*)(smc + OFF_B1);
    int*   sc10 = (int*)(smc + OFF_B2);
    int*   sc11 = (int*)(smc + OFF_B3);
    float* swx  = (float*)(smc + OFF_WXA);
    float* swy  = (float*)(smc + OFF_WYA);
    __shared__ float qscs[8];

    int tid = threadIdx.x, wid = tid >> 5, lane = tid & 31;
    int g = lane >> 2, tg = lane & 3;
    int wm = wid & 3, wn = wid >> 2;
    int rm = wm * 32;
    int bo = blockIdx.y, b = bo / HEADS, o = bo % HEADS;
    int l0 = blockIdx.x * 128;

    const float scale = rsqrtf((float)CCH);
    if (tid < 6) qscs[tid] = wf[o * 12 + tid] * scale;
    if (tid == 6) qscs[6] = bf[o];
    if (tid < 128) {
        int pl = min(l0 + tid, PQ - 1);
        int y = pl / 28, xx = pl % 28;
        float cy = fminf(fmaxf(y * 0.5f - 0.25f, 0.f), 13.f);
        int iy0 = (int)cy; float wy = cy - (float)iy0; int iy1 = min(iy0 + 1, 13);
        float cx = fminf(fmaxf(xx * 0.5f - 0.25f, 0.f), 13.f);
        int ix0 = (int)cx; float wx = cx - (float)ix0; int ix1 = min(ix0 + 1, 13);
        sc00[tid] = (iy0 * 14 + ix0) * TT;
        sc01[tid] = (iy0 * 14 + ix1) * TT;
        sc10[tid] = (iy1 * 14 + ix0) * TT;
        sc11[tid] = (iy1 * 14 + ix1) * TT;
        swx[tid] = wx; swy[tid] = wy;
    }
    __syncthreads();
    const float biasv = qscs[6];

    const float* Qb = Qh + (size_t)b * PQ * CCH;
    const float* Kb = Kh + (size_t)b * PQ * CCH;
    const float* Vb = Vh + (size_t)b * PQ * CCH + o * DH;
    const float* Ro = Rm + (size_t)bo * SS * TT;

    // ---- Q' fill: scaled, bf16, resident for whole block ----
    for (int idx = tid; idx < 128 * 96; idx += 256) {
        int row = idx / 96, c4 = idx % 96, cl = c4 * 4;
        float4 qv = make_float4(0.f, 0.f, 0.f, 0.f);
        if (l0 + row < PQ) qv = *(const float4*)&Qb[(size_t)(l0 + row) * CCH + cl];
        float wqv = qscs[cl >> 6];
        uint2 st;
        st.x = bf2(qv.x * wqv, qv.y * wqv);
        st.y = bf2(qv.z * wqv, qv.w * wqv);
        *(uint2*)&Qp[row * 196 + c4 * 2] = st;
    }

    float m_run[4], s_run[4];
    float av[2][4][4];
    #pragma unroll
    for (int i = 0; i < 4; i++) { m_run[i] = -1e30f; s_run[i] = 0.f; }
    #pragma unroll
    for (int a = 0; a < 2; a++)
        #pragma unroll
        for (int n = 0; n < 4; n++)
            #pragma unroll
            for (int c = 0; c < 4; c++) av[a][n][c] = 0.f;

    for (int kt = 0; kt < 7; kt++) {
        int t0 = kt * 128;
        float sacc[2][8][4];
        #pragma unroll
        for (int a = 0; a < 2; a++)
            #pragma unroll
            for (int n = 0; n < 8; n++)
                #pragma unroll
                for (int c = 0; c < 4; c++) sacc[a][n][c] = 0.f;

        // ===== QK^T: 3 chunks of 128 cols, bf16 m16n8k16 =====
        for (int cc = 0; cc < 3; cc++) {
            int c0 = cc * 128;
            __syncthreads();   // prior consumers of Kp/Pp region done
            for (int idx = tid; idx < 4096; idx += 256) {
                int row = idx >> 5, c4 = idx & 31, cl = c4 * 4;
                float4 kv = make_float4(0.f, 0.f, 0.f, 0.f);
                if (t0 + row < PQ) kv = *(const float4*)&Kb[(size_t)(t0 + row) * CCH + c0 + cl];
                uint2 st;
                st.x = bf2(kv.x, kv.y);
                st.y = bf2(kv.z, kv.w);
                *(uint2*)&Kp[row * 68 + c4 * 2] = st;
            }
            __syncthreads();
            #pragma unroll
            for (int ks = 0; ks < 8; ks++) {
                int kw = ks * 8;
                uint32_t af[2][4];
                #pragma unroll
                for (int mt = 0; mt < 2; mt++) {
                    int r0 = (rm + mt * 16 + g) * 196 + cc * 64 + kw + tg;
                    af[mt][0] = Qp[r0];
                    af[mt][1] = Qp[r0 + 8 * 196];
                    af[mt][2] = Qp[r0 + 4];
                    af[mt][3] = Qp[r0 + 8 * 196 + 4];
                }
                #pragma unroll
                for (int nt = 0; nt < 8; nt++) {
                    int cn = wn * 64 + nt * 8;
                    uint32_t b0 = Kp[(cn + g) * 68 + kw + tg];
                    uint32_t b1 = Kp[(cn + g) * 68 + kw + tg + 4];
                    mma16(sacc[0][nt], af[0], b0, b1);
                    mma16(sacc[1][nt], af[1], b0, b1);
                }
            }
        }

        // ===== bias + bilinear residual + mask, row max =====
        float rmax[4] = {-1e30f, -1e30f, -1e30f, -1e30f};
        #pragma unroll
        for (int mt = 0; mt < 2; mt++)
        #pragma unroll
        for (int half = 0; half < 2; half++) {
            int lr = rm + mt * 16 + g + half * 8;
            int o00 = sc00[lr], o01 = sc01[lr], o10 = sc10[lr], o11 = sc11[lr];
            float wx = swx[lr], wy = swy[lr];
            int hr = mt * 2 + half;
            #pragma unroll
            for (int nt = 0; nt < 8; nt++) {
                int gt = t0 + wn * 64 + nt * 8 + 2 * tg;
                float v0, v1;
                if (gt < PQ) {
                    float2 p00 = *(const float2*)&Ro[o00 + gt];
                    float2 p01 = *(const float2*)&Ro[o01 + gt];
                    float2 p10 = *(const float2*)&Ro[o10 + gt];
                    float2 p11 = *(const float2*)&Ro[o11 + gt];
                    float r0x = p00.x + (p01.x - p00.x) * wx;
                    float r1x = p10.x + (p11.x - p10.x) * wx;
                    float r0y = p00.y + (p01.y - p00.y) * wx;
                    float r1y = p10.y + (p11.y - p10.y) * wx;
                    v0 = sacc[mt][nt][half * 2 + 0] + biasv + r0x + (r1x - r0x) * wy;
                    v1 = sacc[mt][nt][half * 2 + 1] + biasv + r0y + (r1y - r0y) * wy;
                } else { v0 = -1e30f; v1 = -1e30f; }
                sacc[mt][nt][half * 2 + 0] = v0;
                sacc[mt][nt][half * 2 + 1] = v1;
                rmax[hr] = fmaxf(rmax[hr], fmaxf(v0, v1));
            }
        }
        #pragma unroll
        for (int hr = 0; hr < 4; hr++) {
            rmax[hr] = fmaxf(rmax[hr], __shfl_xor_sync(0xffffffffu, rmax[hr], 1));
            rmax[hr] = fmaxf(rmax[hr], __shfl_xor_sync(0xffffffffu, rmax[hr], 2));
        }
        if (tg == 0) {
            #pragma unroll
            for (int hr = 0; hr < 4; hr++)
                redmax[wn * 128 + rm + (hr >> 1) * 16 + g + (hr & 1) * 8] = rmax[hr];
        }
        __syncthreads();

        float corr[4], mnew[4];
        #pragma unroll
        for (int hr = 0; hr < 4; hr++) {
            int lr = rm + (hr >> 1) * 16 + g + (hr & 1) * 8;
            float mt2 = fmaxf(redmax[lr], redmax[128 + lr]);
            mnew[hr] = fmaxf(m_run[hr], mt2);
            corr[hr] = __expf(m_run[hr] - mnew[hr]);
            m_run[hr] = mnew[hr];
        }
        float psum[4] = {0.f, 0.f, 0.f, 0.f};
        #pragma unroll
        for (int mt = 0; mt < 2; mt++)
            #pragma unroll
            for (int nt = 0; nt < 8; nt++)
                #pragma unroll
                for (int c = 0; c < 4; c++) {
                    int hr = mt * 2 + (c >> 1);
                    float e = __expf(sacc[mt][nt][c] - mnew[hr]);
                    sacc[mt][nt][c] = e;
                    psum[hr] += e;
                }
        #pragma unroll
        for (int hr = 0; hr < 4; hr++) {
            psum[hr] += __shfl_xor_sync(0xffffffffu, psum[hr], 1);
            psum[hr] += __shfl_xor_sync(0xffffffffu, psum[hr], 2);
        }
        if (tg == 0) {
            #pragma unroll
            for (int hr = 0; hr < 4; hr++)
                redsum[wn * 128 + rm + (hr >> 1) * 16 + g + (hr & 1) * 8] = psum[hr];
        }
        __syncthreads();
        #pragma unroll
        for (int hr = 0; hr < 4; hr++) {
            int lr = rm + (hr >> 1) * 16 + g + (hr & 1) * 8;
            s_run[hr] = s_run[hr] * corr[hr] + redsum[lr] + redsum[128 + lr];
        }
        #pragma unroll
        for (int mt = 0; mt < 2; mt++)
            #pragma unroll
            for (int nt = 0; nt < 4; nt++)
                #pragma unroll
                for (int c = 0; c < 4; c++)
                    av[mt][nt][c] *= corr[mt * 2 + (c >> 1)];

        // ===== store P (tf32) to smem (aliases K region; safe after syncs) =====
        #pragma unroll
        for (int mt = 0; mt < 2; mt++)
        #pragma unroll
        for (int half = 0; half < 2; half++) {
            int lr = rm + mt * 16 + g + half * 8;
            #pragma unroll
            for (int nt = 0; nt < 8; nt++) {
                uint2 pv;
                pv.x = f2tf(sacc[mt][nt][half * 2 + 0]);
                pv.y = f2tf(sacc[mt][nt][half * 2 + 1]);
                *(uint2*)&Pp[lr * 132 + wn * 64 + nt * 8 + 2 * tg] = pv;
            }
        }
        // ===== V fill (tf32) =====
        for (int idx = tid; idx < 2048; idx += 256) {
            int row = idx >> 4, dl = (idx & 15) * 4;
            float4 vv = make_float4(0.f, 0.f, 0.f, 0.f);
            if (t0 + row < PQ) vv = *(const float4*)&Vb[(size_t)(t0 + row) * CCH + dl];
            uint4 vi;
            vi.x = f2tf(vv.x); vi.y = f2tf(vv.y); vi.z = f2tf(vv.z); vi.w = f2tf(vv.w);
            *(uint4*)&Vp[row * 72 + dl] = vi;
        }
        __syncthreads();

        // ===== AV += P * V (tf32, 16 k-steps over 128 t) =====
        #pragma unroll
        for (int k = 0; k < 16; k++) {
            int kc = k * 8;
            uint32_t af[2][4];
            #pragma unroll
            for (int mt = 0; mt < 2; mt++) {
                int r0 = (rm + mt * 16 + g) * 132 + kc + tg;
                af[mt][0] = Pp[r0];
                af[mt][1] = Pp[r0 + 8 * 132];
                af[mt][2] = Pp[r0 + 4];
                af[mt][3] = Pp[r0 + 8 * 132 + 4];
            }
            #pragma unroll
            for (int nt = 0; nt < 4; nt++) {
                int cn = wn * 32 + nt * 8;
                uint32_t b0 = Vp[(kc + tg) * 72 + cn + g];
                uint32_t b1 = Vp[(kc + tg + 4) * 72 + cn + g];
                mma8(av[0][nt], af[0], b0, b1);
                mma8(av[1][nt], af[1], b0, b1);
            }
        }
    }

    // ===== epilogue =====
    float inv[4];
    #pragma unroll
    for (int hr = 0; hr < 4; hr++) inv[hr] = 1.f / s_run[hr];
    #pragma unroll
    for (int mt = 0; mt < 2; mt++)
    #pragma unroll
    for (int half = 0; half < 2; half++) {
        int gl = l0 + rm + mt * 16 + g + half * 8;
        if (gl < PQ) {
            int hr = mt * 2 + half;
            float* op = AVo + ((size_t)b * PQ + gl) * CCH + o * DH + wn * 32;
            #pragma unroll
            for (int nt = 0; nt < 4; nt++) {
                float2 w2;
                w2.x = av[mt][nt][half * 2 + 0] * inv[hr];
                w2.y = av[mt][nt][half * 2 + 1] * inv[hr];
                *(float2*)&op[nt * 8 + 2 * tg] = w2;
            }
        }
    }
}

// ---------------- launcher ----------------------------------------------------
extern "C" void kernel_launch(void* const* d_in, const int* in_sizes, int n_in,
                              void* d_out, int out_size)
{
    const float* x   = (const float*)d_in[0];
    const float* ra  = (const float*)d_in[1];
    const float* cw  = (const float*)d_in[2];
    const float* lng = (const float*)d_in[3];
    const float* lnb = (const float*)d_in[4];
    const float* wq  = (const float*)d_in[5];
    const float* wk  = (const float*)d_in[6];
    const float* wv  = (const float*)d_in[7];
    const float* wp  = (const float*)d_in[8];
    const float* bp  = (const float*)d_in[9];
    const float* wf  = (const float*)d_in[10];
    const float* bf  = (const float*)d_in[11];
    float* out = (float*)d_out;

    float *Qln, *KV, *Qh, *Kh, *Vh, *Rm, *AV;
    cudaGetSymbolAddress((void**)&Qln, g_Qln);
    cudaGetSymbolAddress((void**)&KV,  g_KV);
    cudaGetSymbolAddress((void**)&Qh,  g_Qh);
    cudaGetSymbolAddress((void**)&Kh,  g_Kh);
    cudaGetSymbolAddress((void**)&Vh,  g_Vh);
    cudaGetSymbolAddress((void**)&Rm,  g_Rm);
    cudaGetSymbolAddress((void**)&AV,  g_AV);

    prep_k<<<dim3(PQ, BATCH), CCH>>>(x, cw, lng, lnb, Qln, KV);

    const int M = BATCH * PQ;
    cudaFuncSetAttribute(gemm_tc, cudaFuncAttributeMaxDynamicSharedMemorySize, GSMT);
    gemm_tc<<<dim3(3, 49), 256, GSMT>>>(Qln, wq, nullptr, Qh, M, CCH);
    gemm_tc<<<dim3(3, 49), 256, GSMT>>>(KV,  wk, nullptr, Kh, M, CCH);
    gemm_tc<<<dim3(3, 49), 256, GSMT>>>(KV,  wv, nullptr, Vh, M, CCH);

    rmix_k<<<dim3(SS, BATCH), 256>>>(ra, wf, Rm);

    cudaFuncSetAttribute(flashmma_k, cudaFuncAttributeMaxDynamicSharedMemorySize, SMT);
    flashmma_k<<<dim3(7, BATCH * HEADS), 256, SMT>>>(Qh, Kh, Vh, Rm, wf, bf, AV);

    gemm2_k<<<dim3(3, 49), 256>>>(AV, wp, bp, out, M, CCH);
}